// round 1
// baseline (speedup 1.0000x reference)
#include <cuda_runtime.h>
#include <cuda_bf16.h>
#include <float.h>
#include <math.h>

// Problem constants
#define B 64
#define IN_DIM 256
#define H 512
#define M 64
#define N 8192
#define SR 3

// Output layout (floats)
#define OUT_H_OFF 0
#define OUT_C_OFF (B*H)                    // 32768
#define OUT_R_OFF (2*B*H)                  // 65536
#define OUT_W_OFF (2*B*H + B*N)            // 589824
#define OUT_M_OFF (2*B*H + 2*B*N)          // 1114112

// Scratch (static device globals — no allocation)
__device__ float g_k[B*M];        // controller key (tanh'd)
__device__ float g_par[B*8];      // beta, g, gamma, s0, s1, s2, nk, pad
__device__ float g_logit[B*N];    // content logits
__device__ float g_mpart[B*8*M];  // M_read partials
__device__ float g_Mread[B*M];
__device__ float g_gates[B*4*H];
__device__ float g_ea[B*2*M];     // e (sigmoided) then a

__device__ __forceinline__ float sigf(float x) { return 1.0f / (1.0f + expf(-x)); }

// ---------------------------------------------------------------------------
// Controller: k = tanh(h@kw^T+kb); cv = h@cw^T+cb; s = softmax(h@sw^T+sb)
// beta = relu(cv0)+1e-4; g = sigmoid(cv1); gamma = relu(cv2)+1.0001; nk=|k|^2
// If ww != null also computes write_all = h@ww^T+wb -> e=sigmoid(first M), a.
// One block per batch, 256 threads.
// ---------------------------------------------------------------------------
__global__ void controller_kernel(const float* __restrict__ hstate,
                                  const float* __restrict__ kw, const float* __restrict__ kb,
                                  const float* __restrict__ cw, const float* __restrict__ cb,
                                  const float* __restrict__ sw, const float* __restrict__ sb,
                                  const float* __restrict__ ww, const float* __restrict__ wb)
{
    int b = blockIdx.x;
    int t = threadIdx.x;
    __shared__ float hs[H];
    __shared__ float ks[M];
    __shared__ float cvs[3];
    __shared__ float ss[3];

    for (int i = t; i < H; i += 256) hs[i] = hstate[b*H + i];
    __syncthreads();

    if (t < M) {
        const float4* w4 = (const float4*)(kw + (size_t)t * H);
        float acc = kb[t];
        #pragma unroll 8
        for (int q = 0; q < H/4; q++) {
            float4 wv = w4[q]; int j = q*4;
            acc += wv.x*hs[j] + wv.y*hs[j+1] + wv.z*hs[j+2] + wv.w*hs[j+3];
        }
        ks[t] = tanhf(acc);
    } else if (t < M + 3) {
        int r = t - M;
        const float4* w4 = (const float4*)(cw + (size_t)r * H);
        float acc = cb[r];
        for (int q = 0; q < H/4; q++) {
            float4 wv = w4[q]; int j = q*4;
            acc += wv.x*hs[j] + wv.y*hs[j+1] + wv.z*hs[j+2] + wv.w*hs[j+3];
        }
        cvs[r] = acc;
    } else if (t < M + 6) {
        int r = t - M - 3;
        const float4* w4 = (const float4*)(sw + (size_t)r * H);
        float acc = sb[r];
        for (int q = 0; q < H/4; q++) {
            float4 wv = w4[q]; int j = q*4;
            acc += wv.x*hs[j] + wv.y*hs[j+1] + wv.z*hs[j+2] + wv.w*hs[j+3];
        }
        ss[r] = acc;
    } else if (ww != nullptr && t >= 70 && t < 70 + 2*M) {
        int r = t - 70;
        const float4* w4 = (const float4*)(ww + (size_t)r * H);
        float acc = wb[r];
        for (int q = 0; q < H/4; q++) {
            float4 wv = w4[q]; int j = q*4;
            acc += wv.x*hs[j] + wv.y*hs[j+1] + wv.z*hs[j+2] + wv.w*hs[j+3];
        }
        g_ea[b*2*M + r] = (r < M) ? sigf(acc) : acc;
    }
    if (ww == nullptr && t < M) g_Mread[b*M + t] = 0.0f;
    __syncthreads();

    if (t < M) g_k[b*M + t] = ks[t];
    if (t == 0) {
        float mx = fmaxf(ss[0], fmaxf(ss[1], ss[2]));
        float e0 = expf(ss[0]-mx), e1 = expf(ss[1]-mx), e2 = expf(ss[2]-mx);
        float tot = e0 + e1 + e2;
        float nk = 0.0f;
        for (int j = 0; j < M; j++) nk += ks[j]*ks[j];
        g_par[b*8 + 0] = fmaxf(cvs[0], 0.0f) + 0.0001f;
        g_par[b*8 + 1] = sigf(cvs[1]);
        g_par[b*8 + 2] = fmaxf(cvs[2], 0.0f) + 1.0001f;
        g_par[b*8 + 3] = e0/tot;
        g_par[b*8 + 4] = e1/tot;
        g_par[b*8 + 5] = e2/tot;
        g_par[b*8 + 6] = nk;
    }
}

// ---------------------------------------------------------------------------
// Content logits: logit[b,n] = beta * (k . Mem[b,n,:]) / (|Mem[b,n,:]|^2 * nk)
// grid (N/256, B), 256 threads: 8 lanes per row, 32 rows per iter, 8 iters.
// ---------------------------------------------------------------------------
__global__ void dot_kernel(const float* __restrict__ Mem)
{
    int b = blockIdx.y;
    int t = threadIdx.x;
    __shared__ float ks[M];
    if (t < M) ks[t] = g_k[b*M + t];
    __syncthreads();
    float beta = g_par[b*8 + 0];
    float nk   = g_par[b*8 + 6];
    int lane8 = t & 7;
    int rowp  = t >> 3;
    int m0 = lane8 * 8;
    float k0=ks[m0],k1=ks[m0+1],k2=ks[m0+2],k3=ks[m0+3];
    float k4=ks[m0+4],k5=ks[m0+5],k6=ks[m0+6],k7=ks[m0+7];
    #pragma unroll
    for (int it = 0; it < 8; it++) {
        int n = blockIdx.x*256 + it*32 + rowp;
        const float4* p = (const float4*)(Mem + ((size_t)b*N + n)*M) + lane8*2;
        float4 v0 = p[0], v1 = p[1];
        float d  = v0.x*k0 + v0.y*k1 + v0.z*k2 + v0.w*k3
                 + v1.x*k4 + v1.y*k5 + v1.z*k6 + v1.w*k7;
        float nm = v0.x*v0.x + v0.y*v0.y + v0.z*v0.z + v0.w*v0.w
                 + v1.x*v1.x + v1.y*v1.y + v1.z*v1.z + v1.w*v1.w;
        #pragma unroll
        for (int o = 4; o; o >>= 1) {
            d  += __shfl_xor_sync(0xffffffffu, d,  o);
            nm += __shfl_xor_sync(0xffffffffu, nm, o);
        }
        if (lane8 == 0) g_logit[b*N + n] = beta * d / (nm * nk);
    }
}

// ---------------------------------------------------------------------------
// Block reductions (1024 threads, 32 warps)
// ---------------------------------------------------------------------------
__device__ __forceinline__ float blockReduceSum(float v, float* red)
{
    #pragma unroll
    for (int o = 16; o; o >>= 1) v += __shfl_xor_sync(0xffffffffu, v, o);
    int w = threadIdx.x >> 5, lane = threadIdx.x & 31;
    if (lane == 0) red[w] = v;
    __syncthreads();
    if (w == 0) {
        v = red[lane];
        #pragma unroll
        for (int o = 16; o; o >>= 1) v += __shfl_xor_sync(0xffffffffu, v, o);
        if (lane == 0) red[0] = v;
    }
    __syncthreads();
    float r = red[0];
    __syncthreads();
    return r;
}

__device__ __forceinline__ float blockReduceMax(float v, float* red)
{
    #pragma unroll
    for (int o = 16; o; o >>= 1) v = fmaxf(v, __shfl_xor_sync(0xffffffffu, v, o));
    int w = threadIdx.x >> 5, lane = threadIdx.x & 31;
    if (lane == 0) red[w] = v;
    __syncthreads();
    if (w == 0) {
        v = red[lane];
        #pragma unroll
        for (int o = 16; o; o >>= 1) v = fmaxf(v, __shfl_xor_sync(0xffffffffu, v, o));
        if (lane == 0) red[0] = v;
    }
    __syncthreads();
    float r = red[0];
    __syncthreads();
    return r;
}

// ---------------------------------------------------------------------------
// Addressing: softmax(logits) -> interpolate -> circular shift -> pow -> norm.
// One block per batch, 1024 threads, 8 values per thread. N in smem.
// ---------------------------------------------------------------------------
__global__ void address_kernel(const float* __restrict__ head_prev,
                               float* __restrict__ out_head)
{
    int b = blockIdx.x, t = threadIdx.x;
    __shared__ float buf[N];
    __shared__ float red[32];
    float g     = g_par[b*8 + 1];
    float gamma = g_par[b*8 + 2];
    float s0    = g_par[b*8 + 3];
    float s1    = g_par[b*8 + 4];
    float s2    = g_par[b*8 + 5];

    const float* lg = g_logit + (size_t)b*N;
    float l[8];
    float vmax = -FLT_MAX;
    #pragma unroll
    for (int i = 0; i < 8; i++) { l[i] = lg[i*1024 + t]; vmax = fmaxf(vmax, l[i]); }
    vmax = blockReduceMax(vmax, red);

    float lsum = 0.0f;
    #pragma unroll
    for (int i = 0; i < 8; i++) { l[i] = expf(l[i] - vmax); lsum += l[i]; }
    float tot = blockReduceSum(lsum, red);
    float inv = 1.0f / tot;

    const float* hp = head_prev + (size_t)b*N;
    #pragma unroll
    for (int i = 0; i < 8; i++) {
        int idx = i*1024 + t;
        buf[idx] = g * (l[i] * inv) + (1.0f - g) * hp[idx];
    }
    __syncthreads();

    float p[8]; float psum = 0.0f;
    #pragma unroll
    for (int i = 0; i < 8; i++) {
        int idx = i*1024 + t;
        float o = s0 * buf[(idx + N - 2) & (N-1)]
                + s1 * buf[(idx + N - 1) & (N-1)]
                + s2 * buf[idx];
        p[i] = powf(o, gamma);
        psum += p[i];
    }
    float tot2 = blockReduceSum(psum, red);
    float inv2 = 1.0f / tot2;
    #pragma unroll
    for (int i = 0; i < 8; i++) out_head[(size_t)b*N + i*1024 + t] = p[i] * inv2;
}

// ---------------------------------------------------------------------------
// M_read partials: part[b,p,m] = sum over chunk-p rows of r_head[b,n]*Mem[b,n,m]
// grid (8, B), 256 threads (8 lanes per row x 32 rows/iter, 32 iters).
// Deterministic (no atomics).
// ---------------------------------------------------------------------------
__global__ void mread_part_kernel(const float* __restrict__ Mem,
                                  const float* __restrict__ rhead)
{
    int b = blockIdx.y;
    int t = threadIdx.x;
    int lane8 = t & 7, rowp = t >> 3;
    __shared__ float sdata[256*8];
    float a0=0,a1=0,a2=0,a3=0,a4=0,a5=0,a6=0,a7=0;
    const float* hp = rhead + (size_t)b*N;
    #pragma unroll 4
    for (int it = 0; it < 32; it++) {
        int n = blockIdx.x*1024 + it*32 + rowp;
        float r = hp[n];
        const float4* p = (const float4*)(Mem + ((size_t)b*N + n)*M) + lane8*2;
        float4 v0 = p[0], v1 = p[1];
        a0 += r*v0.x; a1 += r*v0.y; a2 += r*v0.z; a3 += r*v0.w;
        a4 += r*v1.x; a5 += r*v1.y; a6 += r*v1.z; a7 += r*v1.w;
    }
    float* s = sdata + t*8;
    s[0]=a0; s[1]=a1; s[2]=a2; s[3]=a3; s[4]=a4; s[5]=a5; s[6]=a6; s[7]=a7;
    __syncthreads();
    if (t < 64) {
        int lg = t >> 3, j = t & 7;
        float acc = 0.0f;
        #pragma unroll
        for (int rw = 0; rw < 32; rw++) acc += sdata[((rw<<3) | lg)*8 + j];
        g_mpart[((size_t)b*8 + blockIdx.x)*M + lg*8 + j] = acc;
    }
}

__global__ void mread_reduce_kernel()
{
    int b = blockIdx.x, m = threadIdx.x;
    float acc = 0.0f;
    #pragma unroll
    for (int p = 0; p < 8; p++) acc += g_mpart[((size_t)b*8 + p)*M + m];
    g_Mread[b*M + m] = acc;
}

// ---------------------------------------------------------------------------
// LSTM gates: gates[b,j] = b_ih[j]+b_hh[j] + [inp,M_read]@W_ih[j] + h@W_hh[j]
// grid (4H/4 = 512), block 256: b = t&63, j = blk*4 + t>>6.
// Warps share j (weight broadcast), differ in b.
// ---------------------------------------------------------------------------
__global__ void gates_kernel(const float* __restrict__ inp,
                             const float* __restrict__ h,
                             const float* __restrict__ W_ih,
                             const float* __restrict__ b_ih,
                             const float* __restrict__ W_hh,
                             const float* __restrict__ b_hh)
{
    int t = threadIdx.x;
    int b = t & 63;
    int j = blockIdx.x*4 + (t >> 6);
    float acc = b_ih[j] + b_hh[j];
    const float4* wi = (const float4*)(W_ih + (size_t)j * (IN_DIM + M));
    const float4* xi = (const float4*)(inp + (size_t)b * IN_DIM);
    #pragma unroll 8
    for (int q = 0; q < IN_DIM/4; q++) {
        float4 w = wi[q], x = xi[q];
        acc += w.x*x.x + w.y*x.y + w.z*x.z + w.w*x.w;
    }
    const float4* mr = (const float4*)(g_Mread + (size_t)b * M);
    #pragma unroll
    for (int q = 0; q < M/4; q++) {
        float4 w = wi[IN_DIM/4 + q], x = mr[q];
        acc += w.x*x.x + w.y*x.y + w.z*x.z + w.w*x.w;
    }
    const float4* wh = (const float4*)(W_hh + (size_t)j * H);
    const float4* hx = (const float4*)(h + (size_t)b * H);
    #pragma unroll 8
    for (int q = 0; q < H/4; q++) {
        float4 w = wh[q], x = hx[q];
        acc += w.x*x.x + w.y*x.y + w.z*x.z + w.w*x.w;
    }
    g_gates[(size_t)b*4*H + j] = acc;
}

__global__ void hc_kernel(const float* __restrict__ c,
                          float* __restrict__ out_h,
                          float* __restrict__ out_c)
{
    int b = blockIdx.x, hh = threadIdx.x;
    const float* gb = g_gates + (size_t)b*4*H;
    float ig = gb[hh], fg = gb[H + hh], gg = gb[2*H + hh], og = gb[3*H + hh];
    float cn = sigf(fg) * c[b*H + hh] + sigf(ig) * tanhf(gg);
    float hn = sigf(og) * tanhf(cn);
    out_h[b*H + hh] = hn;
    out_c[b*H + hh] = cn;
}

// ---------------------------------------------------------------------------
// Memory update: M_out = Mem*(1 - w*e) + w*a
// grid (N/256, B), 256 threads, same layout as dot_kernel.
// ---------------------------------------------------------------------------
__global__ void mout_kernel(const float* __restrict__ Mem,
                            const float* __restrict__ whead,
                            float* __restrict__ outM)
{
    int b = blockIdx.y;
    int t = threadIdx.x;
    __shared__ float es[M], as[M];
    if (t < M) es[t] = g_ea[b*2*M + t];
    else if (t < 2*M) as[t - M] = g_ea[b*2*M + t];
    __syncthreads();
    int lane8 = t & 7, rowp = t >> 3;
    int m0 = lane8 * 8;
    float e0=es[m0],e1=es[m0+1],e2=es[m0+2],e3=es[m0+3];
    float e4=es[m0+4],e5=es[m0+5],e6=es[m0+6],e7=es[m0+7];
    float A0=as[m0],A1=as[m0+1],A2=as[m0+2],A3=as[m0+3];
    float A4=as[m0+4],A5=as[m0+5],A6=as[m0+6],A7=as[m0+7];
    #pragma unroll
    for (int it = 0; it < 8; it++) {
        int n = blockIdx.x*256 + it*32 + rowp;
        float w = whead[(size_t)b*N + n];
        size_t off = ((size_t)b*N + n)*M;
        const float4* p = (const float4*)(Mem + off) + lane8*2;
        float4 v0 = p[0], v1 = p[1];
        float4 o0, o1;
        o0.x = v0.x*(1.0f - w*e0) + w*A0;
        o0.y = v0.y*(1.0f - w*e1) + w*A1;
        o0.z = v0.z*(1.0f - w*e2) + w*A2;
        o0.w = v0.w*(1.0f - w*e3) + w*A3;
        o1.x = v1.x*(1.0f - w*e4) + w*A4;
        o1.y = v1.y*(1.0f - w*e5) + w*A5;
        o1.z = v1.z*(1.0f - w*e6) + w*A6;
        o1.w = v1.w*(1.0f - w*e7) + w*A7;
        float4* q = (float4*)(outM + off) + lane8*2;
        q[0] = o0; q[1] = o1;
    }
}

// ---------------------------------------------------------------------------
extern "C" void kernel_launch(void* const* d_in, const int* in_sizes, int n_in,
                              void* d_out, int out_size)
{
    const float* inp    = (const float*)d_in[0];
    const float* h      = (const float*)d_in[1];
    const float* c      = (const float*)d_in[2];
    const float* rhead  = (const float*)d_in[3];
    const float* whead  = (const float*)d_in[4];
    const float* mem    = (const float*)d_in[5];
    const float* W_ih   = (const float*)d_in[6];
    const float* b_ih   = (const float*)d_in[7];
    const float* W_hh   = (const float*)d_in[8];
    const float* b_hh   = (const float*)d_in[9];
    const float* rk_w   = (const float*)d_in[10];
    const float* rk_b   = (const float*)d_in[11];
    const float* rc_w   = (const float*)d_in[12];
    const float* rc_b   = (const float*)d_in[13];
    const float* rs_w   = (const float*)d_in[14];
    const float* rs_b   = (const float*)d_in[15];
    const float* wk_w   = (const float*)d_in[16];
    const float* wk_b   = (const float*)d_in[17];
    const float* wc_w   = (const float*)d_in[18];
    const float* wc_b   = (const float*)d_in[19];
    const float* ws_w   = (const float*)d_in[20];
    const float* ws_b   = (const float*)d_in[21];
    const float* w_w    = (const float*)d_in[22];
    const float* w_b    = (const float*)d_in[23];

    float* out   = (float*)d_out;
    float* out_h = out + OUT_H_OFF;
    float* out_c = out + OUT_C_OFF;
    float* out_r = out + OUT_R_OFF;
    float* out_w = out + OUT_W_OFF;
    float* out_m = out + OUT_M_OFF;

    // --- read phase ---
    controller_kernel<<<B, 256>>>(h, rk_w, rk_b, rc_w, rc_b, rs_w, rs_b, nullptr, nullptr);
    dot_kernel<<<dim3(N/256, B), 256>>>(mem);
    address_kernel<<<B, 1024>>>(rhead, out_r);
    mread_part_kernel<<<dim3(8, B), 256>>>(mem, out_r);
    mread_reduce_kernel<<<B, M>>>();

    // --- LSTM ---
    gates_kernel<<<4*H/4, 256>>>(inp, h, W_ih, b_ih, W_hh, b_hh);
    hc_kernel<<<B, H>>>(c, out_h, out_c);

    // --- write phase ---
    controller_kernel<<<B, 256>>>(out_h, wk_w, wk_b, wc_w, wc_b, ws_w, ws_b, w_w, w_b);
    dot_kernel<<<dim3(N/256, B), 256>>>(mem);
    address_kernel<<<B, 1024>>>(whead, out_w);
    mout_kernel<<<dim3(N/256, B), 256>>>(mem, out_w, out_m);
}

// round 2
// speedup vs baseline: 1.3167x; 1.3167x over previous
#include <cuda_runtime.h>
#include <cuda_bf16.h>
#include <float.h>
#include <math.h>

// Problem constants
#define B 64
#define IN_DIM 256
#define H 512
#define M 64
#define N 8192
#define SR 3
#define GK 832          // IN_DIM + M + H
#define GJ 2048         // 4*H

// Output layout (floats)
#define OUT_H_OFF 0
#define OUT_C_OFF (B*H)
#define OUT_R_OFF (2*B*H)
#define OUT_W_OFF (2*B*H + B*N)
#define OUT_M_OFF (2*B*H + 2*B*N)

#define NCHUNK 16       // mread partial chunks

// Scratch (static device globals — no allocation)
__device__ float g_k[B*M];          // controller key (tanh'd)
__device__ float g_par[B*8];        // beta, g, gamma, s0, s1, s2, nk
__device__ float g_logit[B*N];      // content logits
__device__ float g_mpart[B*NCHUNK*M];
__device__ float g_x[B*GK];         // [inp | M_read | h] for LSTM GEMM
__device__ float g_gates[B*GJ];
__device__ float g_ea[B*2*M];       // e (sigmoided) then a

__device__ __forceinline__ float sigf(float x) { return 1.0f / (1.0f + __expf(-x)); }

// ---------------------------------------------------------------------------
// Controller: k = tanh(h@kw^T+kb); cv = h@cw^T+cb; s = softmax(h@sw^T+sb)
// If ww != null also computes write_all = h@ww^T+wb -> e=sigmoid(first M), a.
// One block per batch, 256 threads.
// ---------------------------------------------------------------------------
__global__ void controller_kernel(const float* __restrict__ hstate,
                                  const float* __restrict__ kw, const float* __restrict__ kb,
                                  const float* __restrict__ cw, const float* __restrict__ cb,
                                  const float* __restrict__ sw, const float* __restrict__ sb,
                                  const float* __restrict__ ww, const float* __restrict__ wb)
{
    int b = blockIdx.x;
    int t = threadIdx.x;
    __shared__ float hs[H];
    __shared__ float ks[M];
    __shared__ float cvs[3];
    __shared__ float ss[3];

    for (int i = t; i < H; i += 256) hs[i] = hstate[b*H + i];
    __syncthreads();

    if (t < M) {
        const float4* w4 = (const float4*)(kw + (size_t)t * H);
        float acc = kb[t];
        #pragma unroll 8
        for (int q = 0; q < H/4; q++) {
            float4 wv = w4[q]; int j = q*4;
            acc += wv.x*hs[j] + wv.y*hs[j+1] + wv.z*hs[j+2] + wv.w*hs[j+3];
        }
        ks[t] = tanhf(acc);
    } else if (t < M + 3) {
        int r = t - M;
        const float4* w4 = (const float4*)(cw + (size_t)r * H);
        float acc = cb[r];
        for (int q = 0; q < H/4; q++) {
            float4 wv = w4[q]; int j = q*4;
            acc += wv.x*hs[j] + wv.y*hs[j+1] + wv.z*hs[j+2] + wv.w*hs[j+3];
        }
        cvs[r] = acc;
    } else if (t < M + 6) {
        int r = t - M - 3;
        const float4* w4 = (const float4*)(sw + (size_t)r * H);
        float acc = sb[r];
        for (int q = 0; q < H/4; q++) {
            float4 wv = w4[q]; int j = q*4;
            acc += wv.x*hs[j] + wv.y*hs[j+1] + wv.z*hs[j+2] + wv.w*hs[j+3];
        }
        ss[r] = acc;
    } else if (ww != nullptr && t >= 70 && t < 70 + 2*M) {
        int r = t - 70;
        const float4* w4 = (const float4*)(ww + (size_t)r * H);
        float acc = wb[r];
        for (int q = 0; q < H/4; q++) {
            float4 wv = w4[q]; int j = q*4;
            acc += wv.x*hs[j] + wv.y*hs[j+1] + wv.z*hs[j+2] + wv.w*hs[j+3];
        }
        g_ea[b*2*M + r] = (r < M) ? sigf(acc) : acc;
    }
    __syncthreads();

    if (t < M) g_k[b*M + t] = ks[t];
    if (t == 0) {
        float mx = fmaxf(ss[0], fmaxf(ss[1], ss[2]));
        float e0 = __expf(ss[0]-mx), e1 = __expf(ss[1]-mx), e2 = __expf(ss[2]-mx);
        float tot = e0 + e1 + e2;
        float nk = 0.0f;
        for (int j = 0; j < M; j++) nk += ks[j]*ks[j];
        g_par[b*8 + 0] = fmaxf(cvs[0], 0.0f) + 0.0001f;
        g_par[b*8 + 1] = sigf(cvs[1]);
        g_par[b*8 + 2] = fmaxf(cvs[2], 0.0f) + 1.0001f;
        g_par[b*8 + 3] = e0/tot;
        g_par[b*8 + 4] = e1/tot;
        g_par[b*8 + 5] = e2/tot;
        g_par[b*8 + 6] = nk;
    }
}

// ---------------------------------------------------------------------------
// Content logits: logit[b,n] = beta * (k . Mem[b,n,:]) / (|Mem[b,n,:]|^2 * nk)
// grid (N/256, B), 256 threads.
// ---------------------------------------------------------------------------
__global__ void dot_kernel(const float* __restrict__ Mem)
{
    int b = blockIdx.y;
    int t = threadIdx.x;
    __shared__ float ks[M];
    if (t < M) ks[t] = g_k[b*M + t];
    __syncthreads();
    float beta = g_par[b*8 + 0];
    float nk   = g_par[b*8 + 6];
    int lane8 = t & 7;
    int rowp  = t >> 3;
    int m0 = lane8 * 8;
    float k0=ks[m0],k1=ks[m0+1],k2=ks[m0+2],k3=ks[m0+3];
    float k4=ks[m0+4],k5=ks[m0+5],k6=ks[m0+6],k7=ks[m0+7];
    #pragma unroll
    for (int it = 0; it < 8; it++) {
        int n = blockIdx.x*256 + it*32 + rowp;
        const float4* p = (const float4*)(Mem + ((size_t)b*N + n)*M) + lane8*2;
        float4 v0 = p[0], v1 = p[1];
        float d  = v0.x*k0 + v0.y*k1 + v0.z*k2 + v0.w*k3
                 + v1.x*k4 + v1.y*k5 + v1.z*k6 + v1.w*k7;
        float nm = v0.x*v0.x + v0.y*v0.y + v0.z*v0.z + v0.w*v0.w
                 + v1.x*v1.x + v1.y*v1.y + v1.z*v1.z + v1.w*v1.w;
        #pragma unroll
        for (int o = 4; o; o >>= 1) {
            d  += __shfl_xor_sync(0xffffffffu, d,  o);
            nm += __shfl_xor_sync(0xffffffffu, nm, o);
        }
        if (lane8 == 0) g_logit[b*N + n] = beta * d / (nm * nk);
    }
}

// ---------------------------------------------------------------------------
__device__ __forceinline__ float blockReduceSum(float v, float* red)
{
    #pragma unroll
    for (int o = 16; o; o >>= 1) v += __shfl_xor_sync(0xffffffffu, v, o);
    int w = threadIdx.x >> 5, lane = threadIdx.x & 31;
    if (lane == 0) red[w] = v;
    __syncthreads();
    if (w == 0) {
        v = red[lane];
        #pragma unroll
        for (int o = 16; o; o >>= 1) v += __shfl_xor_sync(0xffffffffu, v, o);
        if (lane == 0) red[0] = v;
    }
    __syncthreads();
    float r = red[0];
    __syncthreads();
    return r;
}

__device__ __forceinline__ float blockReduceMax(float v, float* red)
{
    #pragma unroll
    for (int o = 16; o; o >>= 1) v = fmaxf(v, __shfl_xor_sync(0xffffffffu, v, o));
    int w = threadIdx.x >> 5, lane = threadIdx.x & 31;
    if (lane == 0) red[w] = v;
    __syncthreads();
    if (w == 0) {
        v = red[lane];
        #pragma unroll
        for (int o = 16; o; o >>= 1) v = fmaxf(v, __shfl_xor_sync(0xffffffffu, v, o));
        if (lane == 0) red[0] = v;
    }
    __syncthreads();
    float r = red[0];
    __syncthreads();
    return r;
}

// ---------------------------------------------------------------------------
// Addressing: softmax -> interpolate -> circular shift -> pow -> normalize
// One block per batch, 1024 threads, 8 values/thread. Fast-math intrinsics.
// ---------------------------------------------------------------------------
__global__ void address_kernel(const float* __restrict__ head_prev,
                               float* __restrict__ out_head)
{
    int b = blockIdx.x, t = threadIdx.x;
    __shared__ float buf[N];
    __shared__ float red[32];
    float g     = g_par[b*8 + 1];
    float gamma = g_par[b*8 + 2];
    float s0    = g_par[b*8 + 3];
    float s1    = g_par[b*8 + 4];
    float s2    = g_par[b*8 + 5];

    const float* lg = g_logit + (size_t)b*N;
    float l[8];
    float vmax = -FLT_MAX;
    #pragma unroll
    for (int i = 0; i < 8; i++) { l[i] = lg[i*1024 + t]; vmax = fmaxf(vmax, l[i]); }
    vmax = blockReduceMax(vmax, red);

    float lsum = 0.0f;
    #pragma unroll
    for (int i = 0; i < 8; i++) { l[i] = __expf(l[i] - vmax); lsum += l[i]; }
    float tot = blockReduceSum(lsum, red);
    float inv = 1.0f / tot;

    const float* hp = head_prev + (size_t)b*N;
    #pragma unroll
    for (int i = 0; i < 8; i++) {
        int idx = i*1024 + t;
        buf[idx] = g * (l[i] * inv) + (1.0f - g) * hp[idx];
    }
    __syncthreads();

    float p[8]; float psum = 0.0f;
    #pragma unroll
    for (int i = 0; i < 8; i++) {
        int idx = i*1024 + t;
        float o = s0 * buf[(idx + N - 2) & (N-1)]
                + s1 * buf[(idx + N - 1) & (N-1)]
                + s2 * buf[idx];
        p[i] = __powf(o, gamma);
        psum += p[i];
    }
    float tot2 = blockReduceSum(psum, red);
    float inv2 = 1.0f / tot2;
    #pragma unroll
    for (int i = 0; i < 8; i++) out_head[(size_t)b*N + i*1024 + t] = p[i] * inv2;
}

// ---------------------------------------------------------------------------
// M_read partials: NCHUNK chunks per batch, deterministic.
// grid (NCHUNK, B), 256 threads.
// ---------------------------------------------------------------------------
__global__ void mread_part_kernel(const float* __restrict__ Mem,
                                  const float* __restrict__ rhead)
{
    int b = blockIdx.y;
    int t = threadIdx.x;
    int lane8 = t & 7, rowp = t >> 3;
    __shared__ float sdata[256*8];
    float a0=0,a1=0,a2=0,a3=0,a4=0,a5=0,a6=0,a7=0;
    const float* hp = rhead + (size_t)b*N;
    const int ROWS = N / NCHUNK;   // 512
    #pragma unroll 4
    for (int it = 0; it < ROWS/32; it++) {
        int n = blockIdx.x*ROWS + it*32 + rowp;
        float r = hp[n];
        const float4* p = (const float4*)(Mem + ((size_t)b*N + n)*M) + lane8*2;
        float4 v0 = p[0], v1 = p[1];
        a0 += r*v0.x; a1 += r*v0.y; a2 += r*v0.z; a3 += r*v0.w;
        a4 += r*v1.x; a5 += r*v1.y; a6 += r*v1.z; a7 += r*v1.w;
    }
    float* s = sdata + t*8;
    s[0]=a0; s[1]=a1; s[2]=a2; s[3]=a3; s[4]=a4; s[5]=a5; s[6]=a6; s[7]=a7;
    __syncthreads();
    if (t < 64) {
        int lg = t >> 3, j = t & 7;
        float acc = 0.0f;
        #pragma unroll
        for (int rw = 0; rw < 32; rw++) acc += sdata[((rw<<3) | lg)*8 + j];
        g_mpart[((size_t)b*NCHUNK + blockIdx.x)*M + lg*8 + j] = acc;
    }
}

// ---------------------------------------------------------------------------
// X prep: g_x[b] = [inp(256) | M_read(64, reduced from partials) | h(512)]
// grid B, 256 threads.
// ---------------------------------------------------------------------------
__global__ void xprep_kernel(const float* __restrict__ inp,
                             const float* __restrict__ h)
{
    int b = blockIdx.x, t = threadIdx.x;
    float* xb = g_x + (size_t)b*GK;
    xb[t] = inp[(size_t)b*IN_DIM + t];
    if (t < M) {
        float a = 0.0f;
        #pragma unroll
        for (int p = 0; p < NCHUNK; p++) a += g_mpart[((size_t)b*NCHUNK + p)*M + t];
        xb[IN_DIM + t] = a;
    }
    #pragma unroll
    for (int i = 0; i < 2; i++) xb[IN_DIM + M + i*256 + t] = h[(size_t)b*H + i*256 + t];
}

// ---------------------------------------------------------------------------
// LSTM gates GEMM: gates[b][j] = X[b] . [W_ih|W_hh][j] + b_ih[j] + b_hh[j]
// C = X(64 x 832) @ W^T(832 x 2048). Tiled: block = 64b x 64j, 256 threads,
// each thread 4x4 register tile. grid 32 (j tiles). K chunks of 32
// (chunks 0-9 -> W_ih, 10-25 -> W_hh; boundary exact at k=320).
// ---------------------------------------------------------------------------
__global__ void gates_gemm_kernel(const float* __restrict__ W_ih,
                                  const float* __restrict__ b_ih,
                                  const float* __restrict__ W_hh,
                                  const float* __restrict__ b_hh)
{
    __shared__ float Xs[64][33];
    __shared__ float Ws[64][33];
    int t  = threadIdx.x;
    int tx = t & 15;          // b-tile index (4 rows each)
    int ty = t >> 4;          // j-tile index (4 rows each)
    int jbase = blockIdx.x * 64;

    int lrow = t >> 2;        // 0..63 load row
    int lcol = (t & 3) * 8;   // 0,8,16,24 load col base

    float acc[4][4];
    #pragma unroll
    for (int i = 0; i < 4; i++)
        #pragma unroll
        for (int j = 0; j < 4; j++) acc[i][j] = 0.0f;

    for (int kc = 0; kc < GK/32; kc++) {
        int k0 = kc * 32;
        // X tile load (coalesced 32B per thread)
        const float* xsrc = g_x + (size_t)lrow*GK + k0 + lcol;
        float4 xa = *(const float4*)xsrc;
        float4 xb = *(const float4*)(xsrc + 4);
        Xs[lrow][lcol+0]=xa.x; Xs[lrow][lcol+1]=xa.y; Xs[lrow][lcol+2]=xa.z; Xs[lrow][lcol+3]=xa.w;
        Xs[lrow][lcol+4]=xb.x; Xs[lrow][lcol+5]=xb.y; Xs[lrow][lcol+6]=xb.z; Xs[lrow][lcol+7]=xb.w;
        // W tile load
        const float* wsrc = (k0 < IN_DIM + M)
            ? (W_ih + (size_t)(jbase + lrow)*(IN_DIM + M) + k0 + lcol)
            : (W_hh + (size_t)(jbase + lrow)*H + (k0 - IN_DIM - M) + lcol);
        float4 wa = *(const float4*)wsrc;
        float4 wb = *(const float4*)(wsrc + 4);
        Ws[lrow][lcol+0]=wa.x; Ws[lrow][lcol+1]=wa.y; Ws[lrow][lcol+2]=wa.z; Ws[lrow][lcol+3]=wa.w;
        Ws[lrow][lcol+4]=wb.x; Ws[lrow][lcol+5]=wb.y; Ws[lrow][lcol+6]=wb.z; Ws[lrow][lcol+7]=wb.w;
        __syncthreads();

        #pragma unroll
        for (int k = 0; k < 32; k++) {
            float xv[4], wv[4];
            #pragma unroll
            for (int i = 0; i < 4; i++) xv[i] = Xs[tx*4 + i][k];
            #pragma unroll
            for (int i = 0; i < 4; i++) wv[i] = Ws[ty*4 + i][k];
            #pragma unroll
            for (int i = 0; i < 4; i++)
                #pragma unroll
                for (int j = 0; j < 4; j++) acc[i][j] += xv[i] * wv[j];
        }
        __syncthreads();
    }

    #pragma unroll
    for (int jj = 0; jj < 4; jj++) {
        int j = jbase + ty*4 + jj;
        float bias = b_ih[j] + b_hh[j];
        #pragma unroll
        for (int i = 0; i < 4; i++) {
            int b = tx*4 + i;
            g_gates[(size_t)b*GJ + j] = acc[i][jj] + bias;
        }
    }
}

__global__ void hc_kernel(const float* __restrict__ c,
                          float* __restrict__ out_h,
                          float* __restrict__ out_c)
{
    int b = blockIdx.x, hh = threadIdx.x;
    const float* gb = g_gates + (size_t)b*GJ;
    float ig = gb[hh], fg = gb[H + hh], gg = gb[2*H + hh], og = gb[3*H + hh];
    float cn = sigf(fg) * c[b*H + hh] + sigf(ig) * tanhf(gg);
    float hn = sigf(og) * tanhf(cn);
    out_h[b*H + hh] = hn;
    out_c[b*H + hh] = cn;
}

// ---------------------------------------------------------------------------
// Memory update: M_out = Mem*(1 - w*e) + w*a    (streaming stores)
// ---------------------------------------------------------------------------
__global__ void mout_kernel(const float* __restrict__ Mem,
                            const float* __restrict__ whead,
                            float* __restrict__ outM)
{
    int b = blockIdx.y;
    int t = threadIdx.x;
    __shared__ float es[M], as[M];
    if (t < M) es[t] = g_ea[b*2*M + t];
    else if (t < 2*M) as[t - M] = g_ea[b*2*M + t];
    __syncthreads();
    int lane8 = t & 7, rowp = t >> 3;
    int m0 = lane8 * 8;
    float e0=es[m0],e1=es[m0+1],e2=es[m0+2],e3=es[m0+3];
    float e4=es[m0+4],e5=es[m0+5],e6=es[m0+6],e7=es[m0+7];
    float A0=as[m0],A1=as[m0+1],A2=as[m0+2],A3=as[m0+3];
    float A4=as[m0+4],A5=as[m0+5],A6=as[m0+6],A7=as[m0+7];
    #pragma unroll
    for (int it = 0; it < 8; it++) {
        int n = blockIdx.x*256 + it*32 + rowp;
        float w = whead[(size_t)b*N + n];
        size_t off = ((size_t)b*N + n)*M;
        const float4* p = (const float4*)(Mem + off) + lane8*2;
        float4 v0 = p[0], v1 = p[1];
        float4 o0, o1;
        o0.x = v0.x*(1.0f - w*e0) + w*A0;
        o0.y = v0.y*(1.0f - w*e1) + w*A1;
        o0.z = v0.z*(1.0f - w*e2) + w*A2;
        o0.w = v0.w*(1.0f - w*e3) + w*A3;
        o1.x = v1.x*(1.0f - w*e4) + w*A4;
        o1.y = v1.y*(1.0f - w*e5) + w*A5;
        o1.z = v1.z*(1.0f - w*e6) + w*A6;
        o1.w = v1.w*(1.0f - w*e7) + w*A7;
        float4* q = (float4*)(outM + off) + lane8*2;
        __stcs(q,     o0);
        __stcs(q + 1, o1);
    }
}

// ---------------------------------------------------------------------------
extern "C" void kernel_launch(void* const* d_in, const int* in_sizes, int n_in,
                              void* d_out, int out_size)
{
    const float* inp    = (const float*)d_in[0];
    const float* h      = (const float*)d_in[1];
    const float* c      = (const float*)d_in[2];
    const float* rhead  = (const float*)d_in[3];
    const float* whead  = (const float*)d_in[4];
    const float* mem    = (const float*)d_in[5];
    const float* W_ih   = (const float*)d_in[6];
    const float* b_ih   = (const float*)d_in[7];
    const float* W_hh   = (const float*)d_in[8];
    const float* b_hh   = (const float*)d_in[9];
    const float* rk_w   = (const float*)d_in[10];
    const float* rk_b   = (const float*)d_in[11];
    const float* rc_w   = (const float*)d_in[12];
    const float* rc_b   = (const float*)d_in[13];
    const float* rs_w   = (const float*)d_in[14];
    const float* rs_b   = (const float*)d_in[15];
    const float* wk_w   = (const float*)d_in[16];
    const float* wk_b   = (const float*)d_in[17];
    const float* wc_w   = (const float*)d_in[18];
    const float* wc_b   = (const float*)d_in[19];
    const float* ws_w   = (const float*)d_in[20];
    const float* ws_b   = (const float*)d_in[21];
    const float* w_w    = (const float*)d_in[22];
    const float* w_b    = (const float*)d_in[23];

    float* out   = (float*)d_out;
    float* out_h = out + OUT_H_OFF;
    float* out_c = out + OUT_C_OFF;
    float* out_r = out + OUT_R_OFF;
    float* out_w = out + OUT_W_OFF;
    float* out_m = out + OUT_M_OFF;

    // --- read phase ---
    controller_kernel<<<B, 256>>>(h, rk_w, rk_b, rc_w, rc_b, rs_w, rs_b, nullptr, nullptr);
    dot_kernel<<<dim3(N/256, B), 256>>>(mem);
    address_kernel<<<B, 1024>>>(rhead, out_r);
    mread_part_kernel<<<dim3(NCHUNK, B), 256>>>(mem, out_r);
    xprep_kernel<<<B, 256>>>(inp, h);

    // --- LSTM ---
    gates_gemm_kernel<<<GJ/64, 256>>>(W_ih, b_ih, W_hh, b_hh);
    hc_kernel<<<B, H>>>(c, out_h, out_c);

    // --- write phase ---
    controller_kernel<<<B, 256>>>(out_h, wk_w, wk_b, wc_w, wc_b, ws_w, ws_b, w_w, w_b);
    dot_kernel<<<dim3(N/256, B), 256>>>(mem);
    address_kernel<<<B, 1024>>>(whead, out_w);
    mout_kernel<<<dim3(N/256, B), 256>>>(mem, out_w, out_m);
}

// round 3
// speedup vs baseline: 1.4352x; 1.0900x over previous
#include <cuda_runtime.h>
#include <cuda_bf16.h>
#include <float.h>
#include <math.h>

// Problem constants
#define B 64
#define IN_DIM 256
#define H 512
#define M 64
#define N 8192
#define SR 3
#define GK 832          // IN_DIM + M + H
#define GJ 2048         // 4*H

// Output layout (floats)
#define OUT_H_OFF 0
#define OUT_C_OFF (B*H)
#define OUT_R_OFF (2*B*H)
#define OUT_W_OFF (2*B*H + B*N)
#define OUT_M_OFF (2*B*H + 2*B*N)

#define NCHUNK 16       // mread partial chunks

// Scratch (static device globals — no allocation)
__device__ float g_k[B*M];          // controller key (tanh'd)
__device__ float g_par[B*8];        // beta, g, gamma, s0, s1, s2, nk
__device__ float g_logit[B*N];      // content logits
__device__ float g_mpart[B*NCHUNK*M];
__device__ float g_x[B*GK];         // [inp | M_read | h] for LSTM GEMM
__device__ float g_gates[B*GJ];
__device__ float g_ea[B*2*M];       // e (sigmoided) then a

__device__ __forceinline__ float sigf(float x) { return 1.0f / (1.0f + __expf(-x)); }

// ---------------------------------------------------------------------------
// Controller: k = tanh(h@kw^T+kb); cv = h@cw^T+cb; s = softmax(h@sw^T+sb)
// If ww != null also computes write_all = h@ww^T+wb -> e=sigmoid(first M), a.
// One block per batch, 256 threads.
// ---------------------------------------------------------------------------
__global__ void controller_kernel(const float* __restrict__ hstate,
                                  const float* __restrict__ kw, const float* __restrict__ kb,
                                  const float* __restrict__ cw, const float* __restrict__ cb,
                                  const float* __restrict__ sw, const float* __restrict__ sb,
                                  const float* __restrict__ ww, const float* __restrict__ wb)
{
    int b = blockIdx.x;
    int t = threadIdx.x;
    __shared__ float hs[H];
    __shared__ float ks[M];
    __shared__ float cvs[3];
    __shared__ float ss[3];

    for (int i = t; i < H; i += 256) hs[i] = hstate[b*H + i];
    __syncthreads();

    if (t < M) {
        const float4* w4 = (const float4*)(kw + (size_t)t * H);
        float acc = kb[t];
        #pragma unroll 8
        for (int q = 0; q < H/4; q++) {
            float4 wv = w4[q]; int j = q*4;
            acc += wv.x*hs[j] + wv.y*hs[j+1] + wv.z*hs[j+2] + wv.w*hs[j+3];
        }
        ks[t] = tanhf(acc);
    } else if (t < M + 3) {
        int r = t - M;
        const float4* w4 = (const float4*)(cw + (size_t)r * H);
        float acc = cb[r];
        for (int q = 0; q < H/4; q++) {
            float4 wv = w4[q]; int j = q*4;
            acc += wv.x*hs[j] + wv.y*hs[j+1] + wv.z*hs[j+2] + wv.w*hs[j+3];
        }
        cvs[r] = acc;
    } else if (t < M + 6) {
        int r = t - M - 3;
        const float4* w4 = (const float4*)(sw + (size_t)r * H);
        float acc = sb[r];
        for (int q = 0; q < H/4; q++) {
            float4 wv = w4[q]; int j = q*4;
            acc += wv.x*hs[j] + wv.y*hs[j+1] + wv.z*hs[j+2] + wv.w*hs[j+3];
        }
        ss[r] = acc;
    } else if (ww != nullptr && t >= 70 && t < 70 + 2*M) {
        int r = t - 70;
        const float4* w4 = (const float4*)(ww + (size_t)r * H);
        float acc = wb[r];
        for (int q = 0; q < H/4; q++) {
            float4 wv = w4[q]; int j = q*4;
            acc += wv.x*hs[j] + wv.y*hs[j+1] + wv.z*hs[j+2] + wv.w*hs[j+3];
        }
        g_ea[b*2*M + r] = (r < M) ? sigf(acc) : acc;
    }
    __syncthreads();

    if (t < M) g_k[b*M + t] = ks[t];
    if (t == 0) {
        float mx = fmaxf(ss[0], fmaxf(ss[1], ss[2]));
        float e0 = __expf(ss[0]-mx), e1 = __expf(ss[1]-mx), e2 = __expf(ss[2]-mx);
        float tot = e0 + e1 + e2;
        float nk = 0.0f;
        for (int j = 0; j < M; j++) nk += ks[j]*ks[j];
        g_par[b*8 + 0] = fmaxf(cvs[0], 0.0f) + 0.0001f;
        g_par[b*8 + 1] = sigf(cvs[1]);
        g_par[b*8 + 2] = fmaxf(cvs[2], 0.0f) + 1.0001f;
        g_par[b*8 + 3] = e0/tot;
        g_par[b*8 + 4] = e1/tot;
        g_par[b*8 + 5] = e2/tot;
        g_par[b*8 + 6] = nk;
    }
}

// ---------------------------------------------------------------------------
// Content logits: logit[b,n] = beta * (k . Mem[b,n,:]) / (|Mem[b,n,:]|^2 * nk)
// grid (N/256, B), 256 threads. FORWARD traversal.
// ---------------------------------------------------------------------------
__global__ void dot_kernel(const float* __restrict__ Mem)
{
    int b = blockIdx.y;
    int t = threadIdx.x;
    __shared__ float ks[M];
    if (t < M) ks[t] = g_k[b*M + t];
    __syncthreads();
    float beta = g_par[b*8 + 0];
    float nk   = g_par[b*8 + 6];
    int lane8 = t & 7;
    int rowp  = t >> 3;
    int m0 = lane8 * 8;
    float k0=ks[m0],k1=ks[m0+1],k2=ks[m0+2],k3=ks[m0+3];
    float k4=ks[m0+4],k5=ks[m0+5],k6=ks[m0+6],k7=ks[m0+7];
    #pragma unroll
    for (int it = 0; it < 8; it++) {
        int n = blockIdx.x*256 + it*32 + rowp;
        const float4* p = (const float4*)(Mem + ((size_t)b*N + n)*M) + lane8*2;
        float4 v0 = p[0], v1 = p[1];
        float d  = v0.x*k0 + v0.y*k1 + v0.z*k2 + v0.w*k3
                 + v1.x*k4 + v1.y*k5 + v1.z*k6 + v1.w*k7;
        float nm = v0.x*v0.x + v0.y*v0.y + v0.z*v0.z + v0.w*v0.w
                 + v1.x*v1.x + v1.y*v1.y + v1.z*v1.z + v1.w*v1.w;
        #pragma unroll
        for (int o = 4; o; o >>= 1) {
            d  += __shfl_xor_sync(0xffffffffu, d,  o);
            nm += __shfl_xor_sync(0xffffffffu, nm, o);
        }
        if (lane8 == 0) g_logit[b*N + n] = beta * d / (nm * nk);
    }
}

// ---------------------------------------------------------------------------
__device__ __forceinline__ float blockReduceSum(float v, float* red)
{
    #pragma unroll
    for (int o = 16; o; o >>= 1) v += __shfl_xor_sync(0xffffffffu, v, o);
    int w = threadIdx.x >> 5, lane = threadIdx.x & 31;
    if (lane == 0) red[w] = v;
    __syncthreads();
    if (w == 0) {
        v = red[lane];
        #pragma unroll
        for (int o = 16; o; o >>= 1) v += __shfl_xor_sync(0xffffffffu, v, o);
        if (lane == 0) red[0] = v;
    }
    __syncthreads();
    float r = red[0];
    __syncthreads();
    return r;
}

__device__ __forceinline__ float blockReduceMax(float v, float* red)
{
    #pragma unroll
    for (int o = 16; o; o >>= 1) v = fmaxf(v, __shfl_xor_sync(0xffffffffu, v, o));
    int w = threadIdx.x >> 5, lane = threadIdx.x & 31;
    if (lane == 0) red[w] = v;
    __syncthreads();
    if (w == 0) {
        v = red[lane];
        #pragma unroll
        for (int o = 16; o; o >>= 1) v = fmaxf(v, __shfl_xor_sync(0xffffffffu, v, o));
        if (lane == 0) red[0] = v;
    }
    __syncthreads();
    float r = red[0];
    __syncthreads();
    return r;
}

// ---------------------------------------------------------------------------
// Addressing: softmax -> interpolate -> circular shift -> pow -> normalize
// One block per batch, 1024 threads, 8 values/thread.
// ---------------------------------------------------------------------------
__global__ void address_kernel(const float* __restrict__ head_prev,
                               float* __restrict__ out_head)
{
    int b = blockIdx.x, t = threadIdx.x;
    __shared__ float buf[N];
    __shared__ float red[32];
    float g     = g_par[b*8 + 1];
    float gamma = g_par[b*8 + 2];
    float s0    = g_par[b*8 + 3];
    float s1    = g_par[b*8 + 4];
    float s2    = g_par[b*8 + 5];

    const float* lg = g_logit + (size_t)b*N;
    float l[8];
    float vmax = -FLT_MAX;
    #pragma unroll
    for (int i = 0; i < 8; i++) { l[i] = lg[i*1024 + t]; vmax = fmaxf(vmax, l[i]); }
    vmax = blockReduceMax(vmax, red);

    float lsum = 0.0f;
    #pragma unroll
    for (int i = 0; i < 8; i++) { l[i] = __expf(l[i] - vmax); lsum += l[i]; }
    float tot = blockReduceSum(lsum, red);
    float inv = 1.0f / tot;

    const float* hp = head_prev + (size_t)b*N;
    #pragma unroll
    for (int i = 0; i < 8; i++) {
        int idx = i*1024 + t;
        buf[idx] = g * (l[i] * inv) + (1.0f - g) * hp[idx];
    }
    __syncthreads();

    float p[8]; float psum = 0.0f;
    #pragma unroll
    for (int i = 0; i < 8; i++) {
        int idx = i*1024 + t;
        float o = s0 * buf[(idx + N - 2) & (N-1)]
                + s1 * buf[(idx + N - 1) & (N-1)]
                + s2 * buf[idx];
        p[i] = __powf(o, gamma);
        psum += p[i];
    }
    float tot2 = blockReduceSum(psum, red);
    float inv2 = 1.0f / tot2;
    #pragma unroll
    for (int i = 0; i < 8; i++) out_head[(size_t)b*N + i*1024 + t] = p[i] * inv2;
}

// ---------------------------------------------------------------------------
// M_read partials. REVERSE traversal (serpentine after forward dot pass).
// grid (NCHUNK, B), 256 threads.
// ---------------------------------------------------------------------------
__global__ void mread_part_kernel(const float* __restrict__ Mem,
                                  const float* __restrict__ rhead)
{
    int chunk = gridDim.x - 1 - blockIdx.x;   // reversed
    int b     = B - 1 - blockIdx.y;           // reversed
    int t = threadIdx.x;
    int lane8 = t & 7, rowp = t >> 3;
    __shared__ float sdata[256*8];
    float a0=0,a1=0,a2=0,a3=0,a4=0,a5=0,a6=0,a7=0;
    const float* hp = rhead + (size_t)b*N;
    const int ROWS = N / NCHUNK;   // 512
    #pragma unroll 4
    for (int it = 0; it < ROWS/32; it++) {
        int n = chunk*ROWS + it*32 + rowp;
        float r = hp[n];
        const float4* p = (const float4*)(Mem + ((size_t)b*N + n)*M) + lane8*2;
        float4 v0 = p[0], v1 = p[1];
        a0 += r*v0.x; a1 += r*v0.y; a2 += r*v0.z; a3 += r*v0.w;
        a4 += r*v1.x; a5 += r*v1.y; a6 += r*v1.z; a7 += r*v1.w;
    }
    float* s = sdata + t*8;
    s[0]=a0; s[1]=a1; s[2]=a2; s[3]=a3; s[4]=a4; s[5]=a5; s[6]=a6; s[7]=a7;
    __syncthreads();
    if (t < 64) {
        int lg = t >> 3, j = t & 7;
        float acc = 0.0f;
        #pragma unroll
        for (int rw = 0; rw < 32; rw++) acc += sdata[((rw<<3) | lg)*8 + j];
        g_mpart[((size_t)b*NCHUNK + chunk)*M + lg*8 + j] = acc;
    }
}

// ---------------------------------------------------------------------------
// X prep: g_x[b] = [inp(256) | M_read(64, reduced from partials) | h(512)]
// ---------------------------------------------------------------------------
__global__ void xprep_kernel(const float* __restrict__ inp,
                             const float* __restrict__ h)
{
    int b = blockIdx.x, t = threadIdx.x;
    float* xb = g_x + (size_t)b*GK;
    xb[t] = inp[(size_t)b*IN_DIM + t];
    if (t < M) {
        float a = 0.0f;
        #pragma unroll
        for (int p = 0; p < NCHUNK; p++) a += g_mpart[((size_t)b*NCHUNK + p)*M + t];
        xb[IN_DIM + t] = a;
    }
    #pragma unroll
    for (int i = 0; i < 2; i++) xb[IN_DIM + M + i*256 + t] = h[(size_t)b*H + i*256 + t];
}

// ---------------------------------------------------------------------------
// LSTM gates GEMM: C = X(64 x 832) @ W^T(832 x 2048) + bias.
// Tile 64b x 32j, 256 threads, thread computes 4x2. grid 64 (j tiles).
// ---------------------------------------------------------------------------
__global__ void gates_gemm_kernel(const float* __restrict__ W_ih,
                                  const float* __restrict__ b_ih,
                                  const float* __restrict__ W_hh,
                                  const float* __restrict__ b_hh)
{
    __shared__ float Xs[64][33];
    __shared__ float Ws[32][33];
    int t  = threadIdx.x;
    int tx = t & 15;          // b-tile (4 rows each)
    int ty = t >> 4;          // j-tile (2 rows each)
    int jbase = blockIdx.x * 32;

    int lrow = t >> 2;        // 0..63 X load row
    int lcol = (t & 3) * 8;   // X load col base
    int wrow = t >> 3;        // 0..31 W load row
    int wcol = (t & 7) * 4;   // W load col base

    float acc[4][2];
    #pragma unroll
    for (int i = 0; i < 4; i++) { acc[i][0] = 0.0f; acc[i][1] = 0.0f; }

    for (int kc = 0; kc < GK/32; kc++) {
        int k0 = kc * 32;
        const float* xsrc = g_x + (size_t)lrow*GK + k0 + lcol;
        float4 xa = *(const float4*)xsrc;
        float4 xb = *(const float4*)(xsrc + 4);
        Xs[lrow][lcol+0]=xa.x; Xs[lrow][lcol+1]=xa.y; Xs[lrow][lcol+2]=xa.z; Xs[lrow][lcol+3]=xa.w;
        Xs[lrow][lcol+4]=xb.x; Xs[lrow][lcol+5]=xb.y; Xs[lrow][lcol+6]=xb.z; Xs[lrow][lcol+7]=xb.w;
        const float* wsrc = (k0 < IN_DIM + M)
            ? (W_ih + (size_t)(jbase + wrow)*(IN_DIM + M) + k0 + wcol)
            : (W_hh + (size_t)(jbase + wrow)*H + (k0 - IN_DIM - M) + wcol);
        float4 wa = *(const float4*)wsrc;
        Ws[wrow][wcol+0]=wa.x; Ws[wrow][wcol+1]=wa.y; Ws[wrow][wcol+2]=wa.z; Ws[wrow][wcol+3]=wa.w;
        __syncthreads();

        #pragma unroll
        for (int k = 0; k < 32; k++) {
            float xv[4], wv[2];
            #pragma unroll
            for (int i = 0; i < 4; i++) xv[i] = Xs[tx*4 + i][k];
            wv[0] = Ws[ty*2 + 0][k];
            wv[1] = Ws[ty*2 + 1][k];
            #pragma unroll
            for (int i = 0; i < 4; i++) {
                acc[i][0] += xv[i] * wv[0];
                acc[i][1] += xv[i] * wv[1];
            }
        }
        __syncthreads();
    }

    #pragma unroll
    for (int jj = 0; jj < 2; jj++) {
        int j = jbase + ty*2 + jj;
        float bias = b_ih[j] + b_hh[j];
        #pragma unroll
        for (int i = 0; i < 4; i++) {
            int b = tx*4 + i;
            g_gates[(size_t)b*GJ + j] = acc[i][jj] + bias;
        }
    }
}

__global__ void hc_kernel(const float* __restrict__ c,
                          float* __restrict__ out_h,
                          float* __restrict__ out_c)
{
    int b = blockIdx.x, hh = threadIdx.x;
    const float* gb = g_gates + (size_t)b*GJ;
    float ig = gb[hh], fg = gb[H + hh], gg = gb[2*H + hh], og = gb[3*H + hh];
    float cn = sigf(fg) * c[b*H + hh] + sigf(ig) * tanhf(gg);
    float hn = sigf(og) * tanhf(cn);
    out_h[b*H + hh] = hn;
    out_c[b*H + hh] = cn;
}

// ---------------------------------------------------------------------------
// Memory update: M_out = Mem*(1 - w*e) + w*a
// REVERSE traversal (serpentine after forward dot(write) pass).
// Streaming stores keep mem's read lines resident in L2.
// ---------------------------------------------------------------------------
__global__ void mout_kernel(const float* __restrict__ Mem,
                            const float* __restrict__ whead,
                            float* __restrict__ outM)
{
    int nblk = gridDim.x - 1 - blockIdx.x;    // reversed
    int b    = B - 1 - blockIdx.y;            // reversed
    int t = threadIdx.x;
    __shared__ float es[M], as[M];
    if (t < M) es[t] = g_ea[b*2*M + t];
    else if (t < 2*M) as[t - M] = g_ea[b*2*M + t];
    __syncthreads();
    int lane8 = t & 7, rowp = t >> 3;
    int m0 = lane8 * 8;
    float e0=es[m0],e1=es[m0+1],e2=es[m0+2],e3=es[m0+3];
    float e4=es[m0+4],e5=es[m0+5],e6=es[m0+6],e7=es[m0+7];
    float A0=as[m0],A1=as[m0+1],A2=as[m0+2],A3=as[m0+3];
    float A4=as[m0+4],A5=as[m0+5],A6=as[m0+6],A7=as[m0+7];
    #pragma unroll
    for (int it = 0; it < 8; it++) {
        int n = nblk*256 + it*32 + rowp;
        float w = whead[(size_t)b*N + n];
        size_t off = ((size_t)b*N + n)*M;
        const float4* p = (const float4*)(Mem + off) + lane8*2;
        float4 v0 = p[0], v1 = p[1];
        float4 o0, o1;
        o0.x = v0.x*(1.0f - w*e0) + w*A0;
        o0.y = v0.y*(1.0f - w*e1) + w*A1;
        o0.z = v0.z*(1.0f - w*e2) + w*A2;
        o0.w = v0.w*(1.0f - w*e3) + w*A3;
        o1.x = v1.x*(1.0f - w*e4) + w*A4;
        o1.y = v1.y*(1.0f - w*e5) + w*A5;
        o1.z = v1.z*(1.0f - w*e6) + w*A6;
        o1.w = v1.w*(1.0f - w*e7) + w*A7;
        float4* q = (float4*)(outM + off) + lane8*2;
        __stcs(q,     o0);
        __stcs(q + 1, o1);
    }
}

// ---------------------------------------------------------------------------
extern "C" void kernel_launch(void* const* d_in, const int* in_sizes, int n_in,
                              void* d_out, int out_size)
{
    const float* inp    = (const float*)d_in[0];
    const float* h      = (const float*)d_in[1];
    const float* c      = (const float*)d_in[2];
    const float* rhead  = (const float*)d_in[3];
    const float* whead  = (const float*)d_in[4];
    const float* mem    = (const float*)d_in[5];
    const float* W_ih   = (const float*)d_in[6];
    const float* b_ih   = (const float*)d_in[7];
    const float* W_hh   = (const float*)d_in[8];
    const float* b_hh   = (const float*)d_in[9];
    const float* rk_w   = (const float*)d_in[10];
    const float* rk_b   = (const float*)d_in[11];
    const float* rc_w   = (const float*)d_in[12];
    const float* rc_b   = (const float*)d_in[13];
    const float* rs_w   = (const float*)d_in[14];
    const float* rs_b   = (const float*)d_in[15];
    const float* wk_w   = (const float*)d_in[16];
    const float* wk_b   = (const float*)d_in[17];
    const float* wc_w   = (const float*)d_in[18];
    const float* wc_b   = (const float*)d_in[19];
    const float* ws_w   = (const float*)d_in[20];
    const float* ws_b   = (const float*)d_in[21];
    const float* w_w    = (const float*)d_in[22];
    const float* w_b    = (const float*)d_in[23];

    float* out   = (float*)d_out;
    float* out_h = out + OUT_H_OFF;
    float* out_c = out + OUT_C_OFF;
    float* out_r = out + OUT_R_OFF;
    float* out_w = out + OUT_W_OFF;
    float* out_m = out + OUT_M_OFF;

    // --- read phase ---
    controller_kernel<<<B, 256>>>(h, rk_w, rk_b, rc_w, rc_b, rs_w, rs_b, nullptr, nullptr);
    dot_kernel<<<dim3(N/256, B), 256>>>(mem);                    // forward
    address_kernel<<<B, 1024>>>(rhead, out_r);
    mread_part_kernel<<<dim3(NCHUNK, B), 256>>>(mem, out_r);     // reverse
    xprep_kernel<<<B, 256>>>(inp, h);

    // --- LSTM ---
    gates_gemm_kernel<<<GJ/32, 256>>>(W_ih, b_ih, W_hh, b_hh);
    hc_kernel<<<B, H>>>(c, out_h, out_c);

    // --- write phase ---
    controller_kernel<<<B, 256>>>(out_h, wk_w, wk_b, wc_w, wc_b, ws_w, ws_b, w_w, w_b);
    dot_kernel<<<dim3(N/256, B), 256>>>(mem);                    // forward
    address_kernel<<<B, 1024>>>(whead, out_w);
    mout_kernel<<<dim3(N/256, B), 256>>>(mem, out_w, out_m);     // reverse
}

// round 4
// speedup vs baseline: 1.5067x; 1.0498x over previous
#include <cuda_runtime.h>
#include <cuda_bf16.h>
#include <float.h>
#include <math.h>

// Problem constants
#define B 64
#define IN_DIM 256
#define H 512
#define M 64
#define N 8192
#define SR 3
#define GJ 2048         // 4*H
#define KPART 768       // inp + h K-columns (gemm-partial)

// Output layout (floats)
#define OUT_H_OFF 0
#define OUT_C_OFF (B*H)
#define OUT_R_OFF (2*B*H)
#define OUT_W_OFF (2*B*H + B*N)
#define OUT_M_OFF (2*B*H + 2*B*N)

#define NCHUNK 16       // mread partial chunks

// Scratch (static device globals — no allocation)
__device__ float g_k[B*M];          // controller key (tanh'd)
__device__ float g_par[B*8];        // beta, g, gamma, s0, s1, s2, nk
__device__ float g_logit[B*N];      // content logits
__device__ float g_mpart[B*NCHUNK*M];
__device__ float g_Mread[B*M];
__device__ float g_gatesT[GJ*B];    // partial gates, TRANSPOSED [j][b]
__device__ float g_ea[B*2*M];       // e (sigmoided) then a

__device__ __forceinline__ float sigf(float x) { return 1.0f / (1.0f + __expf(-x)); }

// ---------------------------------------------------------------------------
// Controller: k = tanh(h@kw^T+kb); cv = h@cw^T+cb; s = softmax(h@sw^T+sb)
// If ww != null also computes write_all = h@ww^T+wb -> e=sigmoid(first M), a.
// One block per batch, 256 threads.
// ---------------------------------------------------------------------------
__global__ void controller_kernel(const float* __restrict__ hstate,
                                  const float* __restrict__ kw, const float* __restrict__ kb,
                                  const float* __restrict__ cw, const float* __restrict__ cb,
                                  const float* __restrict__ sw, const float* __restrict__ sb,
                                  const float* __restrict__ ww, const float* __restrict__ wb)
{
    int b = blockIdx.x;
    int t = threadIdx.x;
    __shared__ float hs[H];
    __shared__ float ks[M];
    __shared__ float cvs[3];
    __shared__ float ss[3];

    for (int i = t; i < H; i += 256) hs[i] = hstate[b*H + i];
    __syncthreads();

    if (t < M) {
        const float4* w4 = (const float4*)(kw + (size_t)t * H);
        float acc = kb[t];
        #pragma unroll 8
        for (int q = 0; q < H/4; q++) {
            float4 wv = w4[q]; int j = q*4;
            acc += wv.x*hs[j] + wv.y*hs[j+1] + wv.z*hs[j+2] + wv.w*hs[j+3];
        }
        ks[t] = tanhf(acc);
    } else if (t < M + 3) {
        int r = t - M;
        const float4* w4 = (const float4*)(cw + (size_t)r * H);
        float acc = cb[r];
        for (int q = 0; q < H/4; q++) {
            float4 wv = w4[q]; int j = q*4;
            acc += wv.x*hs[j] + wv.y*hs[j+1] + wv.z*hs[j+2] + wv.w*hs[j+3];
        }
        cvs[r] = acc;
    } else if (t < M + 6) {
        int r = t - M - 3;
        const float4* w4 = (const float4*)(sw + (size_t)r * H);
        float acc = sb[r];
        for (int q = 0; q < H/4; q++) {
            float4 wv = w4[q]; int j = q*4;
            acc += wv.x*hs[j] + wv.y*hs[j+1] + wv.z*hs[j+2] + wv.w*hs[j+3];
        }
        ss[r] = acc;
    } else if (ww != nullptr && t >= 70 && t < 70 + 2*M) {
        int r = t - 70;
        const float4* w4 = (const float4*)(ww + (size_t)r * H);
        float acc = wb[r];
        for (int q = 0; q < H/4; q++) {
            float4 wv = w4[q]; int j = q*4;
            acc += wv.x*hs[j] + wv.y*hs[j+1] + wv.z*hs[j+2] + wv.w*hs[j+3];
        }
        g_ea[b*2*M + r] = (r < M) ? sigf(acc) : acc;
    }
    __syncthreads();

    if (t < M) g_k[b*M + t] = ks[t];
    if (t == 0) {
        float mx = fmaxf(ss[0], fmaxf(ss[1], ss[2]));
        float e0 = __expf(ss[0]-mx), e1 = __expf(ss[1]-mx), e2 = __expf(ss[2]-mx);
        float tot = e0 + e1 + e2;
        float nk = 0.0f;
        for (int j = 0; j < M; j++) nk += ks[j]*ks[j];
        g_par[b*8 + 0] = fmaxf(cvs[0], 0.0f) + 0.0001f;
        g_par[b*8 + 1] = sigf(cvs[1]);
        g_par[b*8 + 2] = fmaxf(cvs[2], 0.0f) + 1.0001f;
        g_par[b*8 + 3] = e0/tot;
        g_par[b*8 + 4] = e1/tot;
        g_par[b*8 + 5] = e2/tot;
        g_par[b*8 + 6] = nk;
    }
}

// ---------------------------------------------------------------------------
// GEMM-partial (device fn): gatesT[j][b] = bias_j + inp[b]@W_ih[j,:256]
//                                               + h[b]@W_hh[j,:]
// 64 blocks, tile 64b x 32j, 256 threads, thread tile 4b x 2j, K=768.
// Runs CONCURRENTLY with the dot(read) streaming blocks (grafted grid).
// ---------------------------------------------------------------------------
__device__ void gemm_partial(int gbid,
                             const float* __restrict__ inp,
                             const float* __restrict__ h,
                             const float* __restrict__ W_ih,
                             const float* __restrict__ b_ih,
                             const float* __restrict__ W_hh,
                             const float* __restrict__ b_hh)
{
    __shared__ float Xs[64][33];
    __shared__ float Ws[32][33];
    int t  = threadIdx.x;
    int tx = t & 15;          // 4 b rows each
    int ty = t >> 4;          // 2 j rows each
    int jbase = gbid * 32;

    int lrow = t >> 2;        // X load row 0..63
    int lcol = (t & 3) * 8;   // X load col base
    int wrow = t >> 3;        // W load row 0..31
    int wcol = (t & 7) * 4;   // W load col base

    float acc[4][2];
    #pragma unroll
    for (int i = 0; i < 4; i++) { acc[i][0] = 0.0f; acc[i][1] = 0.0f; }

    for (int kc = 0; kc < KPART/32; kc++) {
        int k0 = kc * 32;
        // X tile: inp columns for k<256, h columns after
        const float* xsrc = (k0 < IN_DIM)
            ? (inp + (size_t)lrow*IN_DIM + k0 + lcol)
            : (h   + (size_t)lrow*H + (k0 - IN_DIM) + lcol);
        float4 xa = *(const float4*)xsrc;
        float4 xb = *(const float4*)(xsrc + 4);
        Xs[lrow][lcol+0]=xa.x; Xs[lrow][lcol+1]=xa.y; Xs[lrow][lcol+2]=xa.z; Xs[lrow][lcol+3]=xa.w;
        Xs[lrow][lcol+4]=xb.x; Xs[lrow][lcol+5]=xb.y; Xs[lrow][lcol+6]=xb.z; Xs[lrow][lcol+7]=xb.w;
        // W tile
        const float* wsrc = (k0 < IN_DIM)
            ? (W_ih + (size_t)(jbase + wrow)*(IN_DIM + M) + k0 + wcol)
            : (W_hh + (size_t)(jbase + wrow)*H + (k0 - IN_DIM) + wcol);
        float4 wa = *(const float4*)wsrc;
        Ws[wrow][wcol+0]=wa.x; Ws[wrow][wcol+1]=wa.y; Ws[wrow][wcol+2]=wa.z; Ws[wrow][wcol+3]=wa.w;
        __syncthreads();

        #pragma unroll
        for (int k = 0; k < 32; k++) {
            float xv[4], wv[2];
            #pragma unroll
            for (int i = 0; i < 4; i++) xv[i] = Xs[tx*4 + i][k];
            wv[0] = Ws[ty*2 + 0][k];
            wv[1] = Ws[ty*2 + 1][k];
            #pragma unroll
            for (int i = 0; i < 4; i++) {
                acc[i][0] += xv[i] * wv[0];
                acc[i][1] += xv[i] * wv[1];
            }
        }
        __syncthreads();
    }

    #pragma unroll
    for (int jj = 0; jj < 2; jj++) {
        int j = jbase + ty*2 + jj;
        float bias = b_ih[j] + b_hh[j];
        #pragma unroll
        for (int i = 0; i < 4; i++) {
            int b = tx*4 + i;
            g_gatesT[(size_t)j*B + b] = acc[i][jj] + bias;   // transposed
        }
    }
}

// ---------------------------------------------------------------------------
// Fused dot + grafted GEMM launch.
// bid < 64: gemm-partial (only when do_gemm). bid >= 64: dot tile.
// Dot: logit[b,n] = beta * (k . Mem[b,n,:]) / (|Mem[b,n,:]|^2 * nk). FORWARD.
// ---------------------------------------------------------------------------
__global__ void dot_fused_kernel(const float* __restrict__ Mem,
                                 const float* __restrict__ inp,
                                 const float* __restrict__ h,
                                 const float* __restrict__ W_ih,
                                 const float* __restrict__ b_ih,
                                 const float* __restrict__ W_hh,
                                 const float* __restrict__ b_hh,
                                 int do_gemm)
{
    int bid = blockIdx.x;
    if (bid < 64) {
        if (do_gemm) gemm_partial(bid, inp, h, W_ih, b_ih, W_hh, b_hh);
        return;
    }
    int tile = bid - 64;
    int b  = tile >> 5;
    int xt = tile & 31;
    int t = threadIdx.x;
    __shared__ float ks[M];
    if (t < M) ks[t] = g_k[b*M + t];
    __syncthreads();
    float beta = g_par[b*8 + 0];
    float nk   = g_par[b*8 + 6];
    int lane8 = t & 7;
    int rowp  = t >> 3;
    int m0 = lane8 * 8;
    float k0=ks[m0],k1=ks[m0+1],k2=ks[m0+2],k3=ks[m0+3];
    float k4=ks[m0+4],k5=ks[m0+5],k6=ks[m0+6],k7=ks[m0+7];
    #pragma unroll
    for (int it = 0; it < 8; it++) {
        int n = xt*256 + it*32 + rowp;
        const float4* p = (const float4*)(Mem + ((size_t)b*N + n)*M) + lane8*2;
        float4 v0 = p[0], v1 = p[1];
        float d  = v0.x*k0 + v0.y*k1 + v0.z*k2 + v0.w*k3
                 + v1.x*k4 + v1.y*k5 + v1.z*k6 + v1.w*k7;
        float nm = v0.x*v0.x + v0.y*v0.y + v0.z*v0.z + v0.w*v0.w
                 + v1.x*v1.x + v1.y*v1.y + v1.z*v1.z + v1.w*v1.w;
        #pragma unroll
        for (int o = 4; o; o >>= 1) {
            d  += __shfl_xor_sync(0xffffffffu, d,  o);
            nm += __shfl_xor_sync(0xffffffffu, nm, o);
        }
        if (lane8 == 0) g_logit[b*N + n] = beta * d / (nm * nk);
    }
}

// ---------------------------------------------------------------------------
__device__ __forceinline__ float blockReduceSum(float v, float* red)
{
    #pragma unroll
    for (int o = 16; o; o >>= 1) v += __shfl_xor_sync(0xffffffffu, v, o);
    int w = threadIdx.x >> 5, lane = threadIdx.x & 31;
    if (lane == 0) red[w] = v;
    __syncthreads();
    if (w == 0) {
        v = red[lane];
        #pragma unroll
        for (int o = 16; o; o >>= 1) v += __shfl_xor_sync(0xffffffffu, v, o);
        if (lane == 0) red[0] = v;
    }
    __syncthreads();
    float r = red[0];
    __syncthreads();
    return r;
}

__device__ __forceinline__ float blockReduceMax(float v, float* red)
{
    #pragma unroll
    for (int o = 16; o; o >>= 1) v = fmaxf(v, __shfl_xor_sync(0xffffffffu, v, o));
    int w = threadIdx.x >> 5, lane = threadIdx.x & 31;
    if (lane == 0) red[w] = v;
    __syncthreads();
    if (w == 0) {
        v = red[lane];
        #pragma unroll
        for (int o = 16; o; o >>= 1) v = fmaxf(v, __shfl_xor_sync(0xffffffffu, v, o));
        if (lane == 0) red[0] = v;
    }
    __syncthreads();
    float r = red[0];
    __syncthreads();
    return r;
}

// ---------------------------------------------------------------------------
// Addressing: softmax -> interpolate -> circular shift -> pow -> normalize
// One block per batch, 1024 threads, 8 values/thread.
// ---------------------------------------------------------------------------
__global__ void address_kernel(const float* __restrict__ head_prev,
                               float* __restrict__ out_head)
{
    int b = blockIdx.x, t = threadIdx.x;
    __shared__ float buf[N];
    __shared__ float red[32];
    float g     = g_par[b*8 + 1];
    float gamma = g_par[b*8 + 2];
    float s0    = g_par[b*8 + 3];
    float s1    = g_par[b*8 + 4];
    float s2    = g_par[b*8 + 5];

    const float* lg = g_logit + (size_t)b*N;
    float l[8];
    float vmax = -FLT_MAX;
    #pragma unroll
    for (int i = 0; i < 8; i++) { l[i] = lg[i*1024 + t]; vmax = fmaxf(vmax, l[i]); }
    vmax = blockReduceMax(vmax, red);

    float lsum = 0.0f;
    #pragma unroll
    for (int i = 0; i < 8; i++) { l[i] = __expf(l[i] - vmax); lsum += l[i]; }
    float tot = blockReduceSum(lsum, red);
    float inv = 1.0f / tot;

    const float* hp = head_prev + (size_t)b*N;
    #pragma unroll
    for (int i = 0; i < 8; i++) {
        int idx = i*1024 + t;
        buf[idx] = g * (l[i] * inv) + (1.0f - g) * hp[idx];
    }
    __syncthreads();

    float p[8]; float psum = 0.0f;
    #pragma unroll
    for (int i = 0; i < 8; i++) {
        int idx = i*1024 + t;
        float o = s0 * buf[(idx + N - 2) & (N-1)]
                + s1 * buf[(idx + N - 1) & (N-1)]
                + s2 * buf[idx];
        p[i] = __powf(o, gamma);
        psum += p[i];
    }
    float tot2 = blockReduceSum(psum, red);
    float inv2 = 1.0f / tot2;
    #pragma unroll
    for (int i = 0; i < 8; i++) out_head[(size_t)b*N + i*1024 + t] = p[i] * inv2;
}

// ---------------------------------------------------------------------------
// M_read partials. REVERSE traversal (serpentine after forward dot pass).
// grid (NCHUNK, B), 256 threads.
// ---------------------------------------------------------------------------
__global__ void mread_part_kernel(const float* __restrict__ Mem,
                                  const float* __restrict__ rhead)
{
    int chunk = gridDim.x - 1 - blockIdx.x;   // reversed
    int b     = B - 1 - blockIdx.y;           // reversed
    int t = threadIdx.x;
    int lane8 = t & 7, rowp = t >> 3;
    __shared__ float sdata[256*8];
    float a0=0,a1=0,a2=0,a3=0,a4=0,a5=0,a6=0,a7=0;
    const float* hp = rhead + (size_t)b*N;
    const int ROWS = N / NCHUNK;   // 512
    #pragma unroll 4
    for (int it = 0; it < ROWS/32; it++) {
        int n = chunk*ROWS + it*32 + rowp;
        float r = hp[n];
        const float4* p = (const float4*)(Mem + ((size_t)b*N + n)*M) + lane8*2;
        float4 v0 = p[0], v1 = p[1];
        a0 += r*v0.x; a1 += r*v0.y; a2 += r*v0.z; a3 += r*v0.w;
        a4 += r*v1.x; a5 += r*v1.y; a6 += r*v1.z; a7 += r*v1.w;
    }
    float* s = sdata + t*8;
    s[0]=a0; s[1]=a1; s[2]=a2; s[3]=a3; s[4]=a4; s[5]=a5; s[6]=a6; s[7]=a7;
    __syncthreads();
    if (t < 64) {
        int lg = t >> 3, j = t & 7;
        float acc = 0.0f;
        #pragma unroll
        for (int rw = 0; rw < 32; rw++) acc += sdata[((rw<<3) | lg)*8 + j];
        g_mpart[((size_t)b*NCHUNK + chunk)*M + lg*8 + j] = acc;
    }
}

// ---------------------------------------------------------------------------
// Reduce M_read partials: g_Mread[b][k] = sum_p g_mpart[b][p][k]
// ---------------------------------------------------------------------------
__global__ void mreduce_kernel()
{
    int b = blockIdx.x, k = threadIdx.x;
    float a = 0.0f;
    #pragma unroll
    for (int p = 0; p < NCHUNK; p++) a += g_mpart[((size_t)b*NCHUNK + p)*M + k];
    g_Mread[b*M + k] = a;
}

// ---------------------------------------------------------------------------
// Fixup + LSTM cell: gates = gatesT + M_read @ W_mid; then h_new/c_new.
// grid 64 (h-chunks of 8), 512 threads: b = t&63, hloc = t>>6.
// W_mid = W_ih columns [256,320) of rows j = gate*H + h.
// ---------------------------------------------------------------------------
__global__ void fixup_hc_kernel(const float* __restrict__ W_ih,
                                const float* __restrict__ c,
                                float* __restrict__ out_h,
                                float* __restrict__ out_c)
{
    __shared__ float Wm[32][64];     // 4 gates x 8 h rows, 64 k (broadcast reads)
    __shared__ float Mr[64][65];     // padded: conflict-free lane=b reads
    int t = threadIdx.x;
    int hbase = blockIdx.x * 8;

    // load W_mid: row r = gate*8 + hloc -> W_ih[(gate*H + hbase + hloc)*320 + 256 + k]
    {
        int r = t >> 4;                 // 0..31
        int off = (t & 15) * 4;
        int gate = r >> 3, hloc = r & 7;
        const float4* src = (const float4*)(W_ih + (size_t)(gate*H + hbase + hloc)*(IN_DIM + M) + IN_DIM + off);
        float4 v = *src;
        Wm[r][off+0]=v.x; Wm[r][off+1]=v.y; Wm[r][off+2]=v.z; Wm[r][off+3]=v.w;
    }
    // load M_read
    {
        int row = t >> 3;               // 0..63
        int col = (t & 7) * 8;
        const float4* src = (const float4*)(g_Mread + (size_t)row*M + col);
        float4 v0 = src[0], v1 = src[1];
        Mr[row][col+0]=v0.x; Mr[row][col+1]=v0.y; Mr[row][col+2]=v0.z; Mr[row][col+3]=v0.w;
        Mr[row][col+4]=v1.x; Mr[row][col+5]=v1.y; Mr[row][col+6]=v1.z; Mr[row][col+7]=v1.w;
    }
    __syncthreads();

    int b = t & 63;
    int hloc = t >> 6;
    int hh = hbase + hloc;

    float acc[4];
    #pragma unroll
    for (int g4 = 0; g4 < 4; g4++)
        acc[g4] = g_gatesT[(size_t)(g4*H + hh)*B + b];
    #pragma unroll 8
    for (int k = 0; k < M; k++) {
        float m = Mr[b][k];
        #pragma unroll
        for (int g4 = 0; g4 < 4; g4++) acc[g4] += m * Wm[g4*8 + hloc][k];
    }

    float cn = sigf(acc[1]) * c[(size_t)b*H + hh] + sigf(acc[0]) * tanhf(acc[2]);
    float hn = sigf(acc[3]) * tanhf(cn);
    out_c[(size_t)b*H + hh] = cn;
    out_h[(size_t)b*H + hh] = hn;
}

// ---------------------------------------------------------------------------
// Memory update: M_out = Mem*(1 - w*e) + w*a. REVERSE traversal.
// ---------------------------------------------------------------------------
__global__ void mout_kernel(const float* __restrict__ Mem,
                            const float* __restrict__ whead,
                            float* __restrict__ outM)
{
    int nblk = gridDim.x - 1 - blockIdx.x;    // reversed
    int b    = B - 1 - blockIdx.y;            // reversed
    int t = threadIdx.x;
    __shared__ float es[M], as[M];
    if (t < M) es[t] = g_ea[b*2*M + t];
    else if (t < 2*M) as[t - M] = g_ea[b*2*M + t];
    __syncthreads();
    int lane8 = t & 7, rowp = t >> 3;
    int m0 = lane8 * 8;
    float e0=es[m0],e1=es[m0+1],e2=es[m0+2],e3=es[m0+3];
    float e4=es[m0+4],e5=es[m0+5],e6=es[m0+6],e7=es[m0+7];
    float A0=as[m0],A1=as[m0+1],A2=as[m0+2],A3=as[m0+3];
    float A4=as[m0+4],A5=as[m0+5],A6=as[m0+6],A7=as[m0+7];
    #pragma unroll
    for (int it = 0; it < 8; it++) {
        int n = nblk*256 + it*32 + rowp;
        float w = whead[(size_t)b*N + n];
        size_t off = ((size_t)b*N + n)*M;
        const float4* p = (const float4*)(Mem + off) + lane8*2;
        float4 v0 = p[0], v1 = p[1];
        float4 o0, o1;
        o0.x = v0.x*(1.0f - w*e0) + w*A0;
        o0.y = v0.y*(1.0f - w*e1) + w*A1;
        o0.z = v0.z*(1.0f - w*e2) + w*A2;
        o0.w = v0.w*(1.0f - w*e3) + w*A3;
        o1.x = v1.x*(1.0f - w*e4) + w*A4;
        o1.y = v1.y*(1.0f - w*e5) + w*A5;
        o1.z = v1.z*(1.0f - w*e6) + w*A6;
        o1.w = v1.w*(1.0f - w*e7) + w*A7;
        float4* q = (float4*)(outM + off) + lane8*2;
        __stcs(q,     o0);
        __stcs(q + 1, o1);
    }
}

// ---------------------------------------------------------------------------
extern "C" void kernel_launch(void* const* d_in, const int* in_sizes, int n_in,
                              void* d_out, int out_size)
{
    const float* inp    = (const float*)d_in[0];
    const float* h      = (const float*)d_in[1];
    const float* c      = (const float*)d_in[2];
    const float* rhead  = (const float*)d_in[3];
    const float* whead  = (const float*)d_in[4];
    const float* mem    = (const float*)d_in[5];
    const float* W_ih   = (const float*)d_in[6];
    const float* b_ih   = (const float*)d_in[7];
    const float* W_hh   = (const float*)d_in[8];
    const float* b_hh   = (const float*)d_in[9];
    const float* rk_w   = (const float*)d_in[10];
    const float* rk_b   = (const float*)d_in[11];
    const float* rc_w   = (const float*)d_in[12];
    const float* rc_b   = (const float*)d_in[13];
    const float* rs_w   = (const float*)d_in[14];
    const float* rs_b   = (const float*)d_in[15];
    const float* wk_w   = (const float*)d_in[16];
    const float* wk_b   = (const float*)d_in[17];
    const float* wc_w   = (const float*)d_in[18];
    const float* wc_b   = (const float*)d_in[19];
    const float* ws_w   = (const float*)d_in[20];
    const float* ws_b   = (const float*)d_in[21];
    const float* w_w    = (const float*)d_in[22];
    const float* w_b    = (const float*)d_in[23];

    float* out   = (float*)d_out;
    float* out_h = out + OUT_H_OFF;
    float* out_c = out + OUT_C_OFF;
    float* out_r = out + OUT_R_OFF;
    float* out_w = out + OUT_W_OFF;
    float* out_m = out + OUT_M_OFF;

    // --- read phase (gates-partial GEMM grafted into dot launch) ---
    controller_kernel<<<B, 256>>>(h, rk_w, rk_b, rc_w, rc_b, rs_w, rs_b, nullptr, nullptr);
    dot_fused_kernel<<<64 + B*(N/256), 256>>>(mem, inp, h, W_ih, b_ih, W_hh, b_hh, 1);
    address_kernel<<<B, 1024>>>(rhead, out_r);
    mread_part_kernel<<<dim3(NCHUNK, B), 256>>>(mem, out_r);     // reverse
    mreduce_kernel<<<B, M>>>();
    fixup_hc_kernel<<<H/8, 512>>>(W_ih, c, out_h, out_c);

    // --- write phase ---
    controller_kernel<<<B, 256>>>(out_h, wk_w, wk_b, wc_w, wc_b, ws_w, ws_b, w_w, w_b);
    dot_fused_kernel<<<64 + B*(N/256), 256>>>(mem, inp, h, W_ih, b_ih, W_hh, b_hh, 0);
    address_kernel<<<B, 1024>>>(whead, out_w);
    mout_kernel<<<dim3(N/256, B), 256>>>(mem, out_w, out_m);     // reverse
}

// round 5
// speedup vs baseline: 1.5609x; 1.0359x over previous
#include <cuda_runtime.h>
#include <cuda_bf16.h>
#include <float.h>
#include <math.h>

// Problem constants
#define B 64
#define IN_DIM 256
#define H 512
#define M 64
#define N 8192
#define GJ 2048          // 4*H
#define KPART 768        // inp + h K-columns
#define MCHUNK 64        // mread chunks of 128 rows
#define DTILE 128        // dot/mout tile rows

// Output layout (floats)
#define OUT_C_OFF (B*H)
#define OUT_R_OFF (2*B*H)
#define OUT_W_OFF (2*B*H + B*N)
#define OUT_M_OFF (2*B*H + 2*B*N)

// Scratch (static device globals — no allocation)
__device__ float g_k[B*M];
__device__ __align__(128) float g_par[B*32];  // padded: 1 line per batch
__device__ float g_logit[B*N];
__device__ float g_mpart[B*MCHUNK*M];
__device__ float g_Mread[B*M];
__device__ float g_gatesT[GJ*B];              // partial gates [j][b]
__device__ float g_ea[B*2*M];

// Flags (zero-init; each kernel resets the previous kernel's flags)
__device__ int fA[B];      // K1 controller -> K1 dot        (reset by K2)
__device__ int fB[B];      // K2 address    -> K2 mread      (reset by K3)
__device__ int ctrB[B];    // K2 mread chunk counter         (reset by K3)
__device__ int ctrC;       // K3 fixup      -> K3 controller (reset by K4)
__device__ int fC[B];      // K3 controller -> K3 dot        (reset by K4)
__device__ int fD[B];      // K4 address    -> K4 mout       (reset by K1)

__device__ __forceinline__ float sigf(float x) { return 1.0f / (1.0f + __expf(-x)); }

__device__ __forceinline__ void spin_on(int* f)
{
    if (threadIdx.x == 0) {
        while (atomicAdd(f, 0) == 0) __nanosleep(64);
    }
    __syncthreads();
    __threadfence();
}

__device__ __forceinline__ void release(int* f)
{
    __threadfence();
    __syncthreads();
    if (threadIdx.x == 0) atomicExch(f, 1);
}

// ---------------------------------------------------------------------------
// Block reductions (256 threads, 8 warps)
// ---------------------------------------------------------------------------
__device__ __forceinline__ float bsum(float v, float* red)
{
    #pragma unroll
    for (int o = 16; o; o >>= 1) v += __shfl_xor_sync(0xffffffffu, v, o);
    int t = threadIdx.x;
    if ((t & 31) == 0) red[t >> 5] = v;
    __syncthreads();
    if (t < 8) {
        v = red[t];
        #pragma unroll
        for (int o = 4; o; o >>= 1) v += __shfl_xor_sync(0xffu, v, o);
        if (t == 0) red[0] = v;
    }
    __syncthreads();
    float r = red[0];
    __syncthreads();
    return r;
}

__device__ __forceinline__ float bmax(float v, float* red)
{
    #pragma unroll
    for (int o = 16; o; o >>= 1) v = fmaxf(v, __shfl_xor_sync(0xffffffffu, v, o));
    int t = threadIdx.x;
    if ((t & 31) == 0) red[t >> 5] = v;
    __syncthreads();
    if (t < 8) {
        v = red[t];
        #pragma unroll
        for (int o = 4; o; o >>= 1) v = fmaxf(v, __shfl_xor_sync(0xffu, v, o));
        if (t == 0) red[0] = v;
    }
    __syncthreads();
    float r = red[0];
    __syncthreads();
    return r;
}

// ---------------------------------------------------------------------------
// Controller (device fn, 256 threads, one block per batch)
// ---------------------------------------------------------------------------
__device__ void controller_dev(int b, const float* __restrict__ hstate,
                               const float* __restrict__ kw, const float* __restrict__ kb,
                               const float* __restrict__ cw, const float* __restrict__ cb,
                               const float* __restrict__ sw, const float* __restrict__ sb,
                               const float* __restrict__ ww, const float* __restrict__ wb)
{
    int t = threadIdx.x;
    __shared__ float hs[H];
    __shared__ float ks[M];
    __shared__ float cvs[3];
    __shared__ float ss[3];

    for (int i = t; i < H; i += 256) hs[i] = hstate[(size_t)b*H + i];
    __syncthreads();

    if (t < M) {
        const float4* w4 = (const float4*)(kw + (size_t)t * H);
        float acc = kb[t];
        #pragma unroll 8
        for (int q = 0; q < H/4; q++) {
            float4 wv = w4[q]; int j = q*4;
            acc += wv.x*hs[j] + wv.y*hs[j+1] + wv.z*hs[j+2] + wv.w*hs[j+3];
        }
        ks[t] = tanhf(acc);
    } else if (t < M + 3) {
        int r = t - M;
        const float4* w4 = (const float4*)(cw + (size_t)r * H);
        float acc = cb[r];
        for (int q = 0; q < H/4; q++) {
            float4 wv = w4[q]; int j = q*4;
            acc += wv.x*hs[j] + wv.y*hs[j+1] + wv.z*hs[j+2] + wv.w*hs[j+3];
        }
        cvs[r] = acc;
    } else if (t < M + 6) {
        int r = t - M - 3;
        const float4* w4 = (const float4*)(sw + (size_t)r * H);
        float acc = sb[r];
        for (int q = 0; q < H/4; q++) {
            float4 wv = w4[q]; int j = q*4;
            acc += wv.x*hs[j] + wv.y*hs[j+1] + wv.z*hs[j+2] + wv.w*hs[j+3];
        }
        ss[r] = acc;
    } else if (ww != nullptr && t >= 70 && t < 70 + 2*M) {
        int r = t - 70;
        const float4* w4 = (const float4*)(ww + (size_t)r * H);
        float acc = wb[r];
        for (int q = 0; q < H/4; q++) {
            float4 wv = w4[q]; int j = q*4;
            acc += wv.x*hs[j] + wv.y*hs[j+1] + wv.z*hs[j+2] + wv.w*hs[j+3];
        }
        g_ea[b*2*M + r] = (r < M) ? sigf(acc) : acc;
    }
    __syncthreads();

    if (t < M) g_k[b*M + t] = ks[t];
    if (t == 0) {
        float mx = fmaxf(ss[0], fmaxf(ss[1], ss[2]));
        float e0 = __expf(ss[0]-mx), e1 = __expf(ss[1]-mx), e2 = __expf(ss[2]-mx);
        float tot = e0 + e1 + e2;
        float nk = 0.0f;
        for (int j = 0; j < M; j++) nk += ks[j]*ks[j];
        g_par[b*32 + 0] = fmaxf(cvs[0], 0.0f) + 0.0001f;
        g_par[b*32 + 1] = sigf(cvs[1]);
        g_par[b*32 + 2] = fmaxf(cvs[2], 0.0f) + 1.0001f;
        g_par[b*32 + 3] = e0/tot;
        g_par[b*32 + 4] = e1/tot;
        g_par[b*32 + 5] = e2/tot;
        g_par[b*32 + 6] = nk;
    }
}

// ---------------------------------------------------------------------------
// GEMM-partial: gatesT[j][b] = bias_j + inp[b]@W_ih[j,:256] + h[b]@W_hh[j,:]
// ---------------------------------------------------------------------------
__device__ void gemm_partial(int gbid,
                             const float* __restrict__ inp,
                             const float* __restrict__ h,
                             const float* __restrict__ W_ih,
                             const float* __restrict__ b_ih,
                             const float* __restrict__ W_hh,
                             const float* __restrict__ b_hh)
{
    __shared__ float Xs[64][33];
    __shared__ float Ws[32][33];
    int t  = threadIdx.x;
    int tx = t & 15;
    int ty = t >> 4;
    int jbase = gbid * 32;
    int lrow = t >> 2;
    int lcol = (t & 3) * 8;
    int wrow = t >> 3;
    int wcol = (t & 7) * 4;

    float acc[4][2];
    #pragma unroll
    for (int i = 0; i < 4; i++) { acc[i][0] = 0.0f; acc[i][1] = 0.0f; }

    for (int kc = 0; kc < KPART/32; kc++) {
        int k0 = kc * 32;
        const float* xsrc = (k0 < IN_DIM)
            ? (inp + (size_t)lrow*IN_DIM + k0 + lcol)
            : (h   + (size_t)lrow*H + (k0 - IN_DIM) + lcol);
        float4 xa = *(const float4*)xsrc;
        float4 xb = *(const float4*)(xsrc + 4);
        Xs[lrow][lcol+0]=xa.x; Xs[lrow][lcol+1]=xa.y; Xs[lrow][lcol+2]=xa.z; Xs[lrow][lcol+3]=xa.w;
        Xs[lrow][lcol+4]=xb.x; Xs[lrow][lcol+5]=xb.y; Xs[lrow][lcol+6]=xb.z; Xs[lrow][lcol+7]=xb.w;
        const float* wsrc = (k0 < IN_DIM)
            ? (W_ih + (size_t)(jbase + wrow)*(IN_DIM + M) + k0 + wcol)
            : (W_hh + (size_t)(jbase + wrow)*H + (k0 - IN_DIM) + wcol);
        float4 wa = *(const float4*)wsrc;
        Ws[wrow][wcol+0]=wa.x; Ws[wrow][wcol+1]=wa.y; Ws[wrow][wcol+2]=wa.z; Ws[wrow][wcol+3]=wa.w;
        __syncthreads();
        #pragma unroll
        for (int k = 0; k < 32; k++) {
            float xv[4], wv[2];
            #pragma unroll
            for (int i = 0; i < 4; i++) xv[i] = Xs[tx*4 + i][k];
            wv[0] = Ws[ty*2 + 0][k];
            wv[1] = Ws[ty*2 + 1][k];
            #pragma unroll
            for (int i = 0; i < 4; i++) {
                acc[i][0] += xv[i] * wv[0];
                acc[i][1] += xv[i] * wv[1];
            }
        }
        __syncthreads();
    }
    #pragma unroll
    for (int jj = 0; jj < 2; jj++) {
        int j = jbase + ty*2 + jj;
        float bias = b_ih[j] + b_hh[j];
        #pragma unroll
        for (int i = 0; i < 4; i++)
            g_gatesT[(size_t)j*B + (tx*4 + i)] = acc[i][jj] + bias;
    }
}

// ---------------------------------------------------------------------------
// Dot tile (128 rows): prefetch Mem into regs, spin on flag, then compute.
// logit[b,n] = beta * (k . Mem[b,n,:]) / (|Mem[b,n,:]|^2 * nk)
// ---------------------------------------------------------------------------
__device__ void dot_dev(const float* __restrict__ Mem, int tile, int* flags)
{
    int b  = tile >> 6;
    int xt = tile & 63;
    int t = threadIdx.x;
    int lane8 = t & 7, rowp = t >> 3;

    float4 pf[8];
    size_t base = ((size_t)b*N + xt*DTILE)*M;
    #pragma unroll
    for (int it = 0; it < 4; it++) {
        const float4* p = (const float4*)(Mem + base + (size_t)(it*32 + rowp)*M) + lane8*2;
        pf[it*2]   = p[0];
        pf[it*2+1] = p[1];
    }

    spin_on(&flags[b]);

    int m0 = lane8 * 8;
    float4 ka = *(const float4*)(g_k + b*M + m0);
    float4 kb4 = *(const float4*)(g_k + b*M + m0 + 4);
    float beta = g_par[b*32 + 0];
    float nk   = g_par[b*32 + 6];

    #pragma unroll
    for (int it = 0; it < 4; it++) {
        float4 v0 = pf[it*2], v1 = pf[it*2+1];
        float d  = v0.x*ka.x + v0.y*ka.y + v0.z*ka.z + v0.w*ka.w
                 + v1.x*kb4.x + v1.y*kb4.y + v1.z*kb4.z + v1.w*kb4.w;
        float nm = v0.x*v0.x + v0.y*v0.y + v0.z*v0.z + v0.w*v0.w
                 + v1.x*v1.x + v1.y*v1.y + v1.z*v1.z + v1.w*v1.w;
        #pragma unroll
        for (int o = 4; o; o >>= 1) {
            d  += __shfl_xor_sync(0xffffffffu, d,  o);
            nm += __shfl_xor_sync(0xffffffffu, nm, o);
        }
        if (lane8 == 0) g_logit[(size_t)b*N + xt*DTILE + it*32 + rowp] = beta * d / (nm * nk);
    }
}

// ---------------------------------------------------------------------------
// Address (256 threads): softmax -> interpolate -> shift -> pow -> normalize
// ---------------------------------------------------------------------------
__device__ void address_dev(int b, const float* __restrict__ head_prev,
                            float* __restrict__ out_head)
{
    __shared__ float A[N];       // 32KB
    __shared__ float red[8];
    int t = threadIdx.x;
    float g     = g_par[b*32 + 1];
    float gamma = g_par[b*32 + 2];
    float s0    = g_par[b*32 + 3];
    float s1    = g_par[b*32 + 4];
    float s2    = g_par[b*32 + 5];

    const float* lg = g_logit + (size_t)b*N;
    float vmax = -FLT_MAX;
    #pragma unroll
    for (int i = 0; i < 32; i++) {
        float v = lg[i*256 + t];
        A[i*256 + t] = v;
        vmax = fmaxf(vmax, v);
    }
    vmax = bmax(vmax, red);

    float lsum = 0.0f;
    #pragma unroll
    for (int i = 0; i < 32; i++) {
        int idx = i*256 + t;
        float e = __expf(A[idx] - vmax);
        A[idx] = e;
        lsum += e;
    }
    float inv = 1.0f / bsum(lsum, red);

    const float* hp = head_prev + (size_t)b*N;
    #pragma unroll
    for (int i = 0; i < 32; i++) {
        int idx = i*256 + t;
        A[idx] = g * (A[idx] * inv) + (1.0f - g) * hp[idx];
    }
    __syncthreads();

    float p[32];
    float psum = 0.0f;
    #pragma unroll
    for (int i = 0; i < 32; i++) {
        int idx = i*256 + t;
        float o = s0 * A[(idx + N - 2) & (N-1)]
                + s1 * A[(idx + N - 1) & (N-1)]
                + s2 * A[idx];
        p[i] = __powf(o, gamma);
        psum += p[i];
    }
    float inv2 = 1.0f / bsum(psum, red);
    #pragma unroll
    for (int i = 0; i < 32; i++)
        out_head[(size_t)b*N + i*256 + t] = p[i] * inv2;
}

// ---------------------------------------------------------------------------
// M_read chunk (128 rows, reversed): prefetch Mem, spin, weighted sum.
// Last finishing chunk per b reduces partials -> g_Mread[b].
// ---------------------------------------------------------------------------
__device__ void mread_dev(const float* __restrict__ Mem,
                          const float* __restrict__ rhead, int tile_rev)
{
    int b  = B - 1 - (tile_rev >> 6);
    int ch = (MCHUNK - 1) - (tile_rev & 63);
    int t = threadIdx.x;
    int lane8 = t & 7, rowp = t >> 3;

    float4 pf[8];
    size_t base = ((size_t)b*N + ch*128)*M;
    #pragma unroll
    for (int it = 0; it < 4; it++) {
        const float4* p = (const float4*)(Mem + base + (size_t)(it*32 + rowp)*M) + lane8*2;
        pf[it*2]   = p[0];
        pf[it*2+1] = p[1];
    }

    spin_on(&fB[b]);

    float a0=0,a1=0,a2=0,a3=0,a4=0,a5=0,a6=0,a7=0;
    const float* hp = rhead + (size_t)b*N + ch*128;
    #pragma unroll
    for (int it = 0; it < 4; it++) {
        float r = hp[it*32 + rowp];
        float4 v0 = pf[it*2], v1 = pf[it*2+1];
        a0 += r*v0.x; a1 += r*v0.y; a2 += r*v0.z; a3 += r*v0.w;
        a4 += r*v1.x; a5 += r*v1.y; a6 += r*v1.z; a7 += r*v1.w;
    }

    __shared__ float sdata[256*8];
    float* s = sdata + t*8;
    s[0]=a0; s[1]=a1; s[2]=a2; s[3]=a3; s[4]=a4; s[5]=a5; s[6]=a6; s[7]=a7;
    __syncthreads();
    if (t < 64) {
        int lg2 = t >> 3, j = t & 7;
        float acc = 0.0f;
        #pragma unroll
        for (int rw = 0; rw < 32; rw++) acc += sdata[((rw<<3) | lg2)*8 + j];
        g_mpart[((size_t)b*MCHUNK + ch)*M + lg2*8 + j] = acc;
    }

    // last chunk for this b reduces partials
    __threadfence();
    __syncthreads();
    __shared__ int lastf;
    if (t == 0) lastf = (atomicAdd(&ctrB[b], 1) == MCHUNK - 1) ? 1 : 0;
    __syncthreads();
    if (lastf) {
        __threadfence();
        int k = t & 63, q = t >> 6;
        float a = 0.0f;
        #pragma unroll
        for (int p = 0; p < 16; p++)
            a += g_mpart[((size_t)b*MCHUNK + q*16 + p)*M + k];
        __shared__ float sr[256];
        sr[t] = a;
        __syncthreads();
        if (t < 64) g_Mread[b*M + t] = sr[t] + sr[64+t] + sr[128+t] + sr[192+t];
    }
}

// ---------------------------------------------------------------------------
// Fixup + LSTM: gates = gatesT + M_read @ W_mid; h_new/c_new.  (4 h per block)
// ---------------------------------------------------------------------------
__device__ void fixup_dev(int blk, const float* __restrict__ W_ih,
                          const float* __restrict__ c,
                          float* __restrict__ out_h, float* __restrict__ out_c)
{
    __shared__ float Wm[16][65];
    __shared__ float Mr[64][65];
    int t = threadIdx.x;
    int hbase = blk * 4;

    {
        int r = t >> 4;                 // 0..15
        int off = (t & 15) * 4;
        int gate = r >> 2, hloc = r & 3;
        float4 v = *(const float4*)(W_ih + (size_t)(gate*H + hbase + hloc)*(IN_DIM + M) + IN_DIM + off);
        Wm[r][off+0]=v.x; Wm[r][off+1]=v.y; Wm[r][off+2]=v.z; Wm[r][off+3]=v.w;
    }
    {
        int row = t >> 2;               // 0..63
        int col = (t & 3) * 16;
        const float4* src = (const float4*)(g_Mread + (size_t)row*M + col);
        float4 v0 = src[0], v1 = src[1], v2 = src[2], v3 = src[3];
        Mr[row][col+ 0]=v0.x; Mr[row][col+ 1]=v0.y; Mr[row][col+ 2]=v0.z; Mr[row][col+ 3]=v0.w;
        Mr[row][col+ 4]=v1.x; Mr[row][col+ 5]=v1.y; Mr[row][col+ 6]=v1.z; Mr[row][col+ 7]=v1.w;
        Mr[row][col+ 8]=v2.x; Mr[row][col+ 9]=v2.y; Mr[row][col+10]=v2.z; Mr[row][col+11]=v2.w;
        Mr[row][col+12]=v3.x; Mr[row][col+13]=v3.y; Mr[row][col+14]=v3.z; Mr[row][col+15]=v3.w;
    }
    __syncthreads();

    int b = t & 63;
    int hloc = t >> 6;                  // 0..3
    int hh = hbase + hloc;

    float acc[4];
    #pragma unroll
    for (int g4 = 0; g4 < 4; g4++)
        acc[g4] = g_gatesT[(size_t)(g4*H + hh)*B + b];
    #pragma unroll 8
    for (int k = 0; k < M; k++) {
        float m = Mr[b][k];
        #pragma unroll
        for (int g4 = 0; g4 < 4; g4++) acc[g4] += m * Wm[g4*4 + hloc][k];
    }

    float cn = sigf(acc[1]) * c[(size_t)b*H + hh] + sigf(acc[0]) * tanhf(acc[2]);
    float hn = sigf(acc[3]) * tanhf(cn);
    out_c[(size_t)b*H + hh] = cn;
    out_h[(size_t)b*H + hh] = hn;

    __threadfence();
    __syncthreads();
    if (t == 0) atomicAdd(&ctrC, 1);
}

// ---------------------------------------------------------------------------
// M_out tile (128 rows, reversed): prefetch Mem, spin on whead flag, update.
// ---------------------------------------------------------------------------
__device__ void mout_dev(const float* __restrict__ Mem,
                         const float* __restrict__ whead,
                         float* __restrict__ outM, int tile_rev)
{
    int b  = B - 1 - (tile_rev >> 6);
    int xt = 63 - (tile_rev & 63);
    int t = threadIdx.x;
    int lane8 = t & 7, rowp = t >> 3;

    float4 pf[8];
    size_t base = ((size_t)b*N + xt*DTILE)*M;
    #pragma unroll
    for (int it = 0; it < 4; it++) {
        const float4* p = (const float4*)(Mem + base + (size_t)(it*32 + rowp)*M) + lane8*2;
        pf[it*2]   = p[0];
        pf[it*2+1] = p[1];
    }

    spin_on(&fD[b]);

    int m0 = lane8 * 8;
    float4 e0v = *(const float4*)(g_ea + b*2*M + m0);
    float4 e1v = *(const float4*)(g_ea + b*2*M + m0 + 4);
    float4 a0v = *(const float4*)(g_ea + b*2*M + M + m0);
    float4 a1v = *(const float4*)(g_ea + b*2*M + M + m0 + 4);

    #pragma unroll
    for (int it = 0; it < 4; it++) {
        float w = whead[(size_t)b*N + xt*DTILE + it*32 + rowp];
        float4 v0 = pf[it*2], v1 = pf[it*2+1];
        float4 o0, o1;
        o0.x = v0.x*(1.0f - w*e0v.x) + w*a0v.x;
        o0.y = v0.y*(1.0f - w*e0v.y) + w*a0v.y;
        o0.z = v0.z*(1.0f - w*e0v.z) + w*a0v.z;
        o0.w = v0.w*(1.0f - w*e0v.w) + w*a0v.w;
        o1.x = v1.x*(1.0f - w*e1v.x) + w*a1v.x;
        o1.y = v1.y*(1.0f - w*e1v.y) + w*a1v.y;
        o1.z = v1.z*(1.0f - w*e1v.z) + w*a1v.z;
        o1.w = v1.w*(1.0f - w*e1v.w) + w*a1v.w;
        float4* q = (float4*)(outM + base + (size_t)(it*32 + rowp)*M) + lane8*2;
        __stcs(q,     o0);
        __stcs(q + 1, o1);
    }
}

// ===========================================================================
// K1: controller(read) [0,64) | gemm [64,128) | dot(read) [128, 128+4096)
// ===========================================================================
__global__ void __launch_bounds__(256) k1_kernel(
    const float* __restrict__ Mem, const float* __restrict__ inp,
    const float* __restrict__ h,
    const float* __restrict__ W_ih, const float* __restrict__ b_ih,
    const float* __restrict__ W_hh, const float* __restrict__ b_hh,
    const float* __restrict__ kw, const float* __restrict__ kb,
    const float* __restrict__ cw, const float* __restrict__ cb,
    const float* __restrict__ sw, const float* __restrict__ sb)
{
    int bid = blockIdx.x;
    if (bid < B) {
        if (threadIdx.x == 0) fD[bid] = 0;   // reset K4 flags (prev replay)
        controller_dev(bid, h, kw, kb, cw, cb, sw, sb, nullptr, nullptr);
        release(&fA[bid]);
        return;
    }
    if (bid < 2*B) {
        gemm_partial(bid - B, inp, h, W_ih, b_ih, W_hh, b_hh);
        return;
    }
    dot_dev(Mem, bid - 2*B, fA);
}

// ===========================================================================
// K2: address(read) [0,64) | mread [64, 64+4096)
// ===========================================================================
__global__ void __launch_bounds__(256) k2_kernel(
    const float* __restrict__ Mem,
    const float* __restrict__ rhead_prev, float* __restrict__ out_r)
{
    int bid = blockIdx.x;
    if (bid < B) {
        if (threadIdx.x == 0) fA[bid] = 0;   // reset K1 flags
        address_dev(bid, rhead_prev, out_r);
        release(&fB[bid]);
        return;
    }
    mread_dev(Mem, out_r, bid - B);
}

// ===========================================================================
// K3: fixup [0,128) | controller(write) [128,192) | dot(write) [192, 192+4096)
// ===========================================================================
__global__ void __launch_bounds__(256) k3_kernel(
    const float* __restrict__ Mem,
    const float* __restrict__ W_ih, const float* __restrict__ c,
    float* __restrict__ out_h, float* __restrict__ out_c,
    const float* __restrict__ wk_w, const float* __restrict__ wk_b,
    const float* __restrict__ wc_w, const float* __restrict__ wc_b,
    const float* __restrict__ ws_w, const float* __restrict__ ws_b,
    const float* __restrict__ w_w,  const float* __restrict__ w_b)
{
    int bid = blockIdx.x;
    if (bid < 128) {
        fixup_dev(bid, W_ih, c, out_h, out_c);
        return;
    }
    if (bid < 192) {
        int b = bid - 128;
        if (threadIdx.x == 0) { fB[b] = 0; ctrB[b] = 0; }   // reset K2 flags
        if (threadIdx.x == 0) {
            while (atomicAdd(&ctrC, 0) < 128) __nanosleep(64);
        }
        __syncthreads();
        __threadfence();
        controller_dev(b, out_h, wk_w, wk_b, wc_w, wc_b, ws_w, ws_b, w_w, w_b);
        release(&fC[b]);
        return;
    }
    dot_dev(Mem, bid - 192, fC);
}

// ===========================================================================
// K4: address(write) [0,64) | mout [64, 64+4096)
// ===========================================================================
__global__ void __launch_bounds__(256) k4_kernel(
    const float* __restrict__ Mem,
    const float* __restrict__ whead_prev,
    float* __restrict__ out_w, float* __restrict__ out_m)
{
    int bid = blockIdx.x;
    if (bid < B) {
        if (threadIdx.x == 0) {
            fC[bid] = 0;                      // reset K3 flags
            if (bid == 0) ctrC = 0;
        }
        address_dev(bid, whead_prev, out_w);
        release(&fD[bid]);
        return;
    }
    mout_dev(Mem, out_w, out_m, bid - B);
}

// ---------------------------------------------------------------------------
extern "C" void kernel_launch(void* const* d_in, const int* in_sizes, int n_in,
                              void* d_out, int out_size)
{
    const float* inp    = (const float*)d_in[0];
    const float* h      = (const float*)d_in[1];
    const float* c      = (const float*)d_in[2];
    const float* rhead  = (const float*)d_in[3];
    const float* whead  = (const float*)d_in[4];
    const float* mem    = (const float*)d_in[5];
    const float* W_ih   = (const float*)d_in[6];
    const float* b_ih   = (const float*)d_in[7];
    const float* W_hh   = (const float*)d_in[8];
    const float* b_hh   = (const float*)d_in[9];
    const float* rk_w   = (const float*)d_in[10];
    const float* rk_b   = (const float*)d_in[11];
    const float* rc_w   = (const float*)d_in[12];
    const float* rc_b   = (const float*)d_in[13];
    const float* rs_w   = (const float*)d_in[14];
    const float* rs_b   = (const float*)d_in[15];
    const float* wk_w   = (const float*)d_in[16];
    const float* wk_b   = (const float*)d_in[17];
    const float* wc_w   = (const float*)d_in[18];
    const float* wc_b   = (const float*)d_in[19];
    const float* ws_w   = (const float*)d_in[20];
    const float* ws_b   = (const float*)d_in[21];
    const float* w_w    = (const float*)d_in[22];
    const float* w_b    = (const float*)d_in[23];

    float* out   = (float*)d_out;
    float* out_h = out;
    float* out_c = out + OUT_C_OFF;
    float* out_r = out + OUT_R_OFF;
    float* out_w = out + OUT_W_OFF;
    float* out_m = out + OUT_M_OFF;

    k1_kernel<<<2*B + B*64, 256>>>(mem, inp, h, W_ih, b_ih, W_hh, b_hh,
                                   rk_w, rk_b, rc_w, rc_b, rs_w, rs_b);
    k2_kernel<<<B + B*64, 256>>>(mem, rhead, out_r);
    k3_kernel<<<192 + B*64, 256>>>(mem, W_ih, c, out_h, out_c,
                                   wk_w, wk_b, wc_w, wc_b, ws_w, ws_b, w_w, w_b);
    k4_kernel<<<B + B*64, 256>>>(mem, whead, out_w, out_m);
}